// round 10
// baseline (speedup 1.0000x reference)
#include <cuda_runtime.h>
#include <cstdint>

#define NEGV (-1e30f)
#define LOG2E 1.4426950408889634f
#define LN2   0.6931471805599453f
#define CHUNK 8
#define NCHUNK 16
#define GROWS  8

// Static device scratch (allocation APIs are forbidden).
__device__ float    g_emit[12u * 1024u * 1024u];  // lane-major log2 emissions
__device__ float    g_alpha[1024 * 224];
__device__ float    g_gamma[1024 * 224];
__device__ unsigned g_chunk[NCHUNK];               // gather progress, zero-init
__device__ unsigned g_fb_ctr;                      // fb completion counter

__device__ __forceinline__ float ex2f(float x) {
    float y; asm("ex2.approx.ftz.f32 %0, %1;" : "=f"(y) : "f"(x)); return y;
}
__device__ __forceinline__ float lg2f(float x) {
    float y; asm("lg2.approx.ftz.f32 %0, %1;" : "=f"(y) : "f"(x)); return y;
}
__device__ __forceinline__ float lae3(float x0, float x1, float x2) {
    float hi = fmaxf(x0, fmaxf(x1, x2));
    float lo = fminf(x0, fminf(x1, x2));
    float md = fmaxf(fminf(x0, x1), fminf(fmaxf(x0, x1), x2));
    return hi + lg2f(1.0f + ex2f(md - hi) + ex2f(lo - hi));
}

__device__ __forceinline__ unsigned chunk_rows(int c, int CS, int T, int N) {
    int lo = c * CS;
    int hi = lo + CS; if (hi > T) hi = T;
    int w  = hi - lo; if (w < 0) w = 0;
    return (unsigned)(w * N);
}
__device__ __forceinline__ void ensure_up(int c, int& ready, int CS, int T, int N) {
    if (c > NCHUNK - 1) c = NCHUNK - 1;
    if (threadIdx.x == 0) {
        while (ready < c) {
            int nc = ready + 1;
            if (*((volatile unsigned*)&g_chunk[nc]) >= chunk_rows(nc, CS, T, N))
                ready = nc;
            else __nanosleep(128);
        }
    }
    __syncwarp();
}
__device__ __forceinline__ void ensure_dn(int c, int& ready, int CS, int T, int N) {
    if (c < 0) c = 0;
    if (threadIdx.x == 0) {
        while (ready > c) {
            int nc = ready - 1;
            if (*((volatile unsigned*)&g_chunk[nc]) >= chunk_rows(nc, CS, T, N))
                ready = nc;
            else __nanosleep(128);
        }
    }
    __syncwarp();
}

__device__ __forceinline__ void issue_chunk(const float* eb, size_t tstride,
                                            float (*sm)[CHUNK][256], int lane,
                                            int buf, int i0, int imax,
                                            bool descending, int tbase) {
#pragma unroll
    for (int j = 0; j < CHUNK; ++j) {
        int ii = i0 + j;
        if (ii > imax) ii = imax;
        int tt = descending ? (tbase - ii) : ii;
        const float* src = eb + (size_t)tt * tstride;
        uint32_t dst = (uint32_t)__cvta_generic_to_shared(&sm[buf][j][lane * 8]);
        asm volatile(
            "cp.async.cg.shared.global [%0], [%1], 16;\n\t"
            "cp.async.cg.shared.global [%2], [%3], 16;\n\t"
            :: "r"(dst), "l"(src), "r"(dst + 16), "l"(src + 4));
    }
    asm volatile("cp.async.commit_group;" ::: "memory");
}

// ---------------------------------------------------------------------------
// Gather: ends-first over t, flags per-chunk completion.
// ---------------------------------------------------------------------------
__global__ void gather_kernel(const float* __restrict__ lp,
                              const int*   __restrict__ targets,
                              int N, int C, int L, int S, int T, int CS) {
    const int g    = blockIdx.x;
    const int j    = threadIdx.x;       // 0..255
    const int lane = j >> 3;
    const int idx  = j & 7;
    const int s    = 7 * lane + idx;

    int ts[GROWS]; bool ok[GROWS];
#pragma unroll
    for (int k = 0; k < GROWS; ++k) {
        int r = g * GROWS + k;
        ok[k] = (r < T * N);
        int zt = 0, n = 0;
        if (ok[k]) { zt = r / N; n = r % N; }
        int t = (zt & 1) ? (T - 1 - (zt >> 1)) : (zt >> 1);
        ts[k] = t;
        if (ok[k]) {
            int tn = t * N + n;
            int lab = 0;
            if (idx < 7 && s < S && (s & 1))
                lab = __ldg(&targets[n * L + (s >> 1)]);
            float e = NEGV;
            if (idx < 7 && s < S)
                e = __ldg(lp + (size_t)tn * C + lab) * LOG2E;
            g_emit[(size_t)tn * 256 + j] = e;
        }
    }
    __syncthreads();
    __threadfence();
    if (threadIdx.x == 0) {
#pragma unroll
        for (int k = 0; k < GROWS; ++k)
            if (ok[k]) atomicAdd(&g_chunk[ts[k] / CS], 1u);
    }
}

// ---------------------------------------------------------------------------
// fb: forward/backward recursion, 1 warp per CTA, polls gather progress.
// Last block combines (per-n logsumexp), reduces, writes out, resets flags.
// ---------------------------------------------------------------------------
__global__ void __launch_bounds__(32, 1)
fb_kernel(const int* __restrict__ targets,
          const int* __restrict__ il,
          const int* __restrict__ tl,
          float*     __restrict__ out,
          int N, int L, int T, int CS) {
    __shared__ float sm[2][CHUNK][256];

    const bool fwd = (blockIdx.x < (unsigned)N);
    const int  n    = fwd ? blockIdx.x : (blockIdx.x - N);
    const int  lane = threadIdx.x;
    const int  S    = 2 * L + 1;

    const int ilen  = il[n];
    const int s_end = 2 * tl[n];
    const int m     = (ilen - 1) >> 1;

    const float* eb      = g_emit + (size_t)n * 256 + lane * 8;
    const size_t tstride = (size_t)N * 256;

    float a[7];

    if (fwd) {
        int ready = -1;
        bool skip[7];
#pragma unroll
        for (int i = 0; i < 7; ++i) {
            int s = 7 * lane + i;
            skip[i] = false;
            if (s < S && (s & 1) && s >= 3)
                skip[i] = (__ldg(&targets[n * L + (s >> 1)]) !=
                           __ldg(&targets[n * L + (s >> 1) - 1]));
        }
        ensure_up(0, ready, CS, T, N);
#pragma unroll
        for (int i = 0; i < 7; ++i) {
            int s = 7 * lane + i;
            a[i] = (s <= 1) ? __ldg(eb + i) : NEGV;
        }
        if (m >= 1) {
            int mt0 = CHUNK     < m ? CHUNK     : m;
            int mt1 = 2 * CHUNK < m ? 2 * CHUNK : m;
            ensure_up(mt0 / CS, ready, CS, T, N);
            issue_chunk(eb, tstride, sm, lane, 0, 1, m, false, 0);
            ensure_up(mt1 / CS, ready, CS, T, N);
            issue_chunk(eb, tstride, sm, lane, 1, 1 + CHUNK, m, false, 0);
            int t = 1, buf = 0;
            while (t <= m) {
                asm volatile("cp.async.wait_group 1;" ::: "memory");
                __syncwarp();
                float4 E0[CHUNK], E1[CHUNK];
#pragma unroll
                for (int j = 0; j < CHUNK; ++j) {
                    E0[j] = *(const float4*)&sm[buf][j][lane * 8];
                    E1[j] = *(const float4*)&sm[buf][j][lane * 8 + 4];
                }
                __syncwarp();
                int mt = t + 3 * CHUNK - 1; if (mt > m) mt = m;
                ensure_up(mt / CS, ready, CS, T, N);
                issue_chunk(eb, tstride, sm, lane, buf, t + 2 * CHUNK, m, false, 0);
                buf ^= 1;
#pragma unroll
                for (int j = 0; j < CHUNK; ++j) {
                    if (t <= m) {
                        float e[7] = {E0[j].x, E0[j].y, E0[j].z, E0[j].w,
                                      E1[j].x, E1[j].y, E1[j].z};
                        float h6 = __shfl_up_sync(0xffffffffu, a[6], 1);
                        float h5 = __shfl_up_sync(0xffffffffu, a[5], 1);
                        if (lane == 0) { h5 = NEGV; h6 = NEGV; }
#pragma unroll
                        for (int i = 6; i >= 0; --i) {
                            float x0 = a[i];
                            float x1 = (i >= 1) ? a[i - 1] : h6;
                            float x2 = (i >= 2) ? a[i - 2] : ((i == 1) ? h6 : h5);
                            x2 = skip[i] ? x2 : NEGV;
                            a[i] = lae3(x0, x1, x2) + e[i];
                        }
                        ++t;
                    }
                }
            }
        }
#pragma unroll
        for (int i = 0; i < 7; ++i)
            g_alpha[n * 224 + 7 * lane + i] = a[i];
    } else {
        int ready = NCHUNK;
        bool bskip[7];
#pragma unroll
        for (int i = 0; i < 7; ++i) {
            int s = 7 * lane + i;
            bskip[i] = false;
            if (s < S && (s & 1) && (s >> 1) + 1 <= L - 1)
                bskip[i] = (__ldg(&targets[n * L + (s >> 1)]) !=
                            __ldg(&targets[n * L + (s >> 1) + 1]));
        }
        if (ilen == 1) {
            ensure_dn((ilen - 1) / CS, ready, CS, T, N);
#pragma unroll
            for (int i = 0; i < 7; ++i) {
                int s = 7 * lane + i;
                a[i] = (s == s_end || (s_end >= 1 && s == s_end - 1)) ? 0.0f : NEGV;
            }
        } else {
            ensure_dn((ilen - 1) / CS, ready, CS, T, N);
#pragma unroll
            for (int i = 0; i < 7; ++i) {
                int s = 7 * lane + i;
                float e = __ldg(eb + (size_t)(ilen - 1) * tstride + i);
                a[i] = (s == s_end || (s_end >= 1 && s == s_end - 1)) ? e : NEGV;
            }
            const int K = ilen - 2 - m;
            if (K >= 1) {
                int d0 = CHUNK     < K ? CHUNK     : K;
                int d1 = 2 * CHUNK < K ? 2 * CHUNK : K;
                ensure_dn((ilen - 1 - d0) / CS, ready, CS, T, N);
                issue_chunk(eb, tstride, sm, lane, 0, 1, K, true, ilen - 1);
                ensure_dn((ilen - 1 - d1) / CS, ready, CS, T, N);
                issue_chunk(eb, tstride, sm, lane, 1, 1 + CHUNK, K, true, ilen - 1);
                int k = 1, buf = 0;
                while (k <= K) {
                    asm volatile("cp.async.wait_group 1;" ::: "memory");
                    __syncwarp();
                    float4 E0[CHUNK], E1[CHUNK];
#pragma unroll
                    for (int j = 0; j < CHUNK; ++j) {
                        E0[j] = *(const float4*)&sm[buf][j][lane * 8];
                        E1[j] = *(const float4*)&sm[buf][j][lane * 8 + 4];
                    }
                    __syncwarp();
                    int dd = k + 3 * CHUNK - 1; if (dd > K) dd = K;
                    ensure_dn((ilen - 1 - dd) / CS, ready, CS, T, N);
                    issue_chunk(eb, tstride, sm, lane, buf, k + 2 * CHUNK, K,
                                true, ilen - 1);
                    buf ^= 1;
#pragma unroll
                    for (int j = 0; j < CHUNK; ++j) {
                        if (k <= K) {
                            float e[7] = {E0[j].x, E0[j].y, E0[j].z, E0[j].w,
                                          E1[j].x, E1[j].y, E1[j].z};
                            float h0 = __shfl_down_sync(0xffffffffu, a[0], 1);
                            float h1 = __shfl_down_sync(0xffffffffu, a[1], 1);
                            if (lane == 31) { h0 = NEGV; h1 = NEGV; }
#pragma unroll
                            for (int i = 0; i <= 6; ++i) {
                                float x0 = a[i];
                                float x1 = (i <= 5) ? a[i + 1] : h0;
                                float x2 = (i <= 4) ? a[i + 2] : ((i == 5) ? h0 : h1);
                                x2 = bskip[i] ? x2 : NEGV;
                                a[i] = lae3(x0, x1, x2) + e[i];
                            }
                            ++k;
                        }
                    }
                }
            }
            // gamma: one transition-only step (no emission)
            {
                float h0 = __shfl_down_sync(0xffffffffu, a[0], 1);
                float h1 = __shfl_down_sync(0xffffffffu, a[1], 1);
                if (lane == 31) { h0 = NEGV; h1 = NEGV; }
                float na[7];
#pragma unroll
                for (int i = 0; i <= 6; ++i) {
                    float x0 = a[i];
                    float x1 = (i <= 5) ? a[i + 1] : h0;
                    float x2 = (i <= 4) ? a[i + 2] : ((i == 5) ? h0 : h1);
                    x2 = bskip[i] ? x2 : NEGV;
                    na[i] = lae3(x0, x1, x2);
                }
#pragma unroll
                for (int i = 0; i < 7; ++i) a[i] = na[i];
            }
        }
#pragma unroll
        for (int i = 0; i < 7; ++i)
            g_gamma[n * 224 + 7 * lane + i] = a[i];
    }

    // ---- finisher: last fb block combines, reduces, resets ----
    __threadfence();
    unsigned done = 0;
    if (lane == 0) done = (atomicAdd(&g_fb_ctr, 1u) == (unsigned)(2 * N) - 1u);
    done = __shfl_sync(0xffffffffu, done, 0);
    if (done) {
        __threadfence();
        float acc = 0.0f;
        for (int nn = 0; nn < N; ++nn) {
            float v[7];
            float mx = -3.4e38f;
#pragma unroll
            for (int k = 0; k < 7; ++k) {
                v[k] = g_alpha[nn * 224 + lane + 32 * k]
                     + g_gamma[nn * 224 + lane + 32 * k];
                mx = fmaxf(mx, v[k]);
            }
#pragma unroll
            for (int o = 16; o > 0; o >>= 1)
                mx = fmaxf(mx, __shfl_xor_sync(0xffffffffu, mx, o));
            float sum = 0.0f;
#pragma unroll
            for (int k = 0; k < 7; ++k) sum += ex2f(v[k] - mx);
#pragma unroll
            for (int o = 16; o > 0; o >>= 1)
                sum += __shfl_xor_sync(0xffffffffu, sum, o);
            float tot = (mx + lg2f(sum)) * LN2;
            if (lane == 0 && tot > -1e29f) acc += tot;
        }
        if (lane == 0) {
            out[0] = -acc;
            for (int c = 0; c < NCHUNK; ++c) g_chunk[c] = 0u;
            g_fb_ctr = 0u;
            __threadfence();
        }
    }
}

extern "C" void kernel_launch(void* const* d_in, const int* in_sizes, int n_in,
                              void* d_out, int out_size) {
    const float* lp      = (const float*)d_in[0];
    const int*   targets = (const int*)d_in[1];
    const int*   il      = (const int*)d_in[2];
    const int*   tl      = (const int*)d_in[3];

    const int N = in_sizes[2];
    const int L = in_sizes[1] / N;        // 100
    const int C = 1024;                   // fixed for this problem id
    const int T = in_sizes[0] / (N * C);  // 1500
    const int S = 2 * L + 1;              // 201
    const int CS = (T + NCHUNK - 1) / NCHUNK;

    // Fork a non-blocking stream so gather runs CONCURRENTLY with fb.
    // (NonBlocking is required: legacy-stream implicit sync would serialize
    //  and deadlock fb's polling in the eager correctness run.)
    cudaStream_t sG;
    cudaStreamCreateWithFlags(&sG, cudaStreamNonBlocking);
    cudaEvent_t evF, evJ;
    cudaEventCreateWithFlags(&evF, cudaEventDisableTiming);
    cudaEventCreateWithFlags(&evJ, cudaEventDisableTiming);

    cudaEventRecord(evF, 0);
    cudaStreamWaitEvent(sG, evF, 0);

    const int gather_blocks = (T * N + GROWS - 1) / GROWS;
    gather_kernel<<<gather_blocks, 256, 0, sG>>>(lp, targets, N, C, L, S, T, CS);
    fb_kernel<<<2 * N, 32>>>(targets, il, tl, (float*)d_out, N, L, T, CS);

    cudaEventRecord(evJ, sG);
    cudaStreamWaitEvent(0, evJ, 0);
    // Stream/events intentionally not destroyed: kernel_launch is called only
    // a handful of times (correctness + capture); the captured graph does not
    // reference them at replay.
}

// round 11
// speedup vs baseline: 2.1020x; 2.1020x over previous
#include <cuda_runtime.h>
#include <cuda_fp16.h>
#include <cstdint>

#define NEGV (-1e30f)
#define LOG2E 1.4426950408889634f
#define LN2   0.6931471805599453f
#define CHUNK 8

// Static device scratch (allocation APIs are forbidden).
__device__ float    g_emit[12u * 1024u * 1024u];  // lane-major log2 emissions
__device__ float    g_alpha[1024 * 224];
__device__ float    g_gamma[1024 * 224];
__device__ unsigned g_fb_ctr;                      // zero-init; reset each call

__device__ __forceinline__ float ex2f(float x) {
    float y; asm("ex2.approx.ftz.f32 %0, %1;" : "=f"(y) : "f"(x)); return y;
}
__device__ __forceinline__ float lg2f(float x) {
    float y; asm("lg2.approx.ftz.f32 %0, %1;" : "=f"(y) : "f"(x)); return y;
}
// Packed: returns ex2(a) + ex2(b) using ONE f16x2 MUFU op.
__device__ __forceinline__ float ex2sum(float a, float b) {
    __half2 h = __floats2half2_rn(a, b);     // overflow -> -inf -> ex2 = 0
    uint32_t u = *(uint32_t*)&h, r;
    asm("ex2.approx.f16x2 %0, %1;" : "=r"(r) : "r"(u));
    __half2 e = *(__half2*)&r;
    float2 f = __half22float2(e);
    return f.x + f.y;
}
// 3-way logaddexp (log2 domain): 2 MUFU (1 ex2x2 + 1 lg2).
__device__ __forceinline__ float lae3(float x0, float x1, float x2) {
    float hi = fmaxf(x0, fmaxf(x1, x2));
    float lo = fminf(x0, fminf(x1, x2));
    float md = fmaxf(fminf(x0, x1), fminf(fmaxf(x0, x1), x2));
    return hi + lg2f(1.0f + ex2sum(md - hi, lo - hi));
}

// ---------------------------------------------------------------------------
// Phase 1: parallel emission gather + relayout + log2 scaling.
// ---------------------------------------------------------------------------
__global__ void gather_kernel(const float* __restrict__ lp,
                              const int*   __restrict__ targets,
                              int N, int C, int L, int S) {
    const int tn   = blockIdx.x;
    const int n    = tn % N;
    const int j    = threadIdx.x;       // 0..255
    const int lane = j >> 3;
    const int idx  = j & 7;
    const int s    = 7 * lane + idx;

    float e = NEGV;
    if (idx < 7 && s < S) {
        int lab = 0;
        if (s & 1) lab = __ldg(&targets[n * L + (s >> 1)]);
        e = __ldg(lp + (size_t)tn * C + lab) * LOG2E;
    }
    g_emit[(size_t)tn * 256 + j] = e;
}

// ---------------------------------------------------------------------------
// Phase 2: forward + backward halves, one warp per CTA, 2N CTAs concurrent.
// cp.async double-buffered shared FIFO; whole chunk staged to registers.
// Last block to finish combines (per-n logsumexp) + fixed-order reduce.
// ---------------------------------------------------------------------------
__device__ __forceinline__ void issue_chunk(const float* eb, size_t tstride,
                                            float (*sm)[CHUNK][256], int lane,
                                            int buf, int i0, int imax,
                                            bool descending, int tbase) {
#pragma unroll
    for (int j = 0; j < CHUNK; ++j) {
        int ii = i0 + j;
        if (ii > imax) ii = imax;
        int tt = descending ? (tbase - ii) : ii;
        const float* src = eb + (size_t)tt * tstride;
        uint32_t dst = (uint32_t)__cvta_generic_to_shared(&sm[buf][j][lane * 8]);
        asm volatile(
            "cp.async.cg.shared.global [%0], [%1], 16;\n\t"
            "cp.async.cg.shared.global [%2], [%3], 16;\n\t"
            :: "r"(dst), "l"(src), "r"(dst + 16), "l"(src + 4));
    }
    asm volatile("cp.async.commit_group;" ::: "memory");
}

__global__ void __launch_bounds__(32, 1)
fb_kernel(const int* __restrict__ targets,
          const int* __restrict__ il,
          const int* __restrict__ tl,
          float*     __restrict__ out,
          int N, int L) {
    __shared__ float sm[2][CHUNK][256];

    const bool fwd = (blockIdx.x < (unsigned)N);
    const int  n    = fwd ? blockIdx.x : (blockIdx.x - N);
    const int  lane = threadIdx.x;
    const int  S    = 2 * L + 1;

    const int ilen  = il[n];
    const int s_end = 2 * tl[n];
    const int m     = (ilen - 1) >> 1;

    const float* eb      = g_emit + (size_t)n * 256 + lane * 8;
    const size_t tstride = (size_t)N * 256;

    float a[7];

    if (fwd) {
        bool skip[7];
#pragma unroll
        for (int i = 0; i < 7; ++i) {
            int s = 7 * lane + i;
            skip[i] = false;
            if (s < S && (s & 1) && s >= 3)
                skip[i] = (__ldg(&targets[n * L + (s >> 1)]) !=
                           __ldg(&targets[n * L + (s >> 1) - 1]));
        }
#pragma unroll
        for (int i = 0; i < 7; ++i) {
            int s = 7 * lane + i;
            a[i] = (s <= 1) ? __ldg(eb + i) : NEGV;
        }
        if (m >= 1) {
            issue_chunk(eb, tstride, sm, lane, 0, 1, m, false, 0);
            issue_chunk(eb, tstride, sm, lane, 1, 1 + CHUNK, m, false, 0);
            int t = 1, buf = 0;
            while (t <= m) {
                asm volatile("cp.async.wait_group 1;" ::: "memory");
                __syncwarp();
                float4 E0[CHUNK], E1[CHUNK];
#pragma unroll
                for (int j = 0; j < CHUNK; ++j) {
                    E0[j] = *(const float4*)&sm[buf][j][lane * 8];
                    E1[j] = *(const float4*)&sm[buf][j][lane * 8 + 4];
                }
                __syncwarp();
                issue_chunk(eb, tstride, sm, lane, buf, t + 2 * CHUNK, m, false, 0);
                buf ^= 1;
#pragma unroll
                for (int j = 0; j < CHUNK; ++j) {
                    if (t <= m) {
                        float e[7] = {E0[j].x, E0[j].y, E0[j].z, E0[j].w,
                                      E1[j].x, E1[j].y, E1[j].z};
                        float h6 = __shfl_up_sync(0xffffffffu, a[6], 1);
                        float h5 = __shfl_up_sync(0xffffffffu, a[5], 1);
                        if (lane == 0) { h5 = NEGV; h6 = NEGV; }
#pragma unroll
                        for (int i = 6; i >= 0; --i) {
                            float x0 = a[i];
                            float x1 = (i >= 1) ? a[i - 1] : h6;
                            float x2 = (i >= 2) ? a[i - 2] : ((i == 1) ? h6 : h5);
                            x2 = skip[i] ? x2 : NEGV;
                            a[i] = lae3(x0, x1, x2) + e[i];
                        }
                        ++t;
                    }
                }
            }
        }
#pragma unroll
        for (int i = 0; i < 7; ++i)
            g_alpha[n * 224 + 7 * lane + i] = a[i];
    } else {
        bool bskip[7];
#pragma unroll
        for (int i = 0; i < 7; ++i) {
            int s = 7 * lane + i;
            bskip[i] = false;
            if (s < S && (s & 1) && (s >> 1) + 1 <= L - 1)
                bskip[i] = (__ldg(&targets[n * L + (s >> 1)]) !=
                            __ldg(&targets[n * L + (s >> 1) + 1]));
        }
        if (ilen == 1) {
#pragma unroll
            for (int i = 0; i < 7; ++i) {
                int s = 7 * lane + i;
                a[i] = (s == s_end || (s_end >= 1 && s == s_end - 1)) ? 0.0f : NEGV;
            }
        } else {
#pragma unroll
            for (int i = 0; i < 7; ++i) {
                int s = 7 * lane + i;
                float e = __ldg(eb + (size_t)(ilen - 1) * tstride + i);
                a[i] = (s == s_end || (s_end >= 1 && s == s_end - 1)) ? e : NEGV;
            }
            const int K = ilen - 2 - m;
            if (K >= 1) {
                issue_chunk(eb, tstride, sm, lane, 0, 1, K, true, ilen - 1);
                issue_chunk(eb, tstride, sm, lane, 1, 1 + CHUNK, K, true, ilen - 1);
                int k = 1, buf = 0;
                while (k <= K) {
                    asm volatile("cp.async.wait_group 1;" ::: "memory");
                    __syncwarp();
                    float4 E0[CHUNK], E1[CHUNK];
#pragma unroll
                    for (int j = 0; j < CHUNK; ++j) {
                        E0[j] = *(const float4*)&sm[buf][j][lane * 8];
                        E1[j] = *(const float4*)&sm[buf][j][lane * 8 + 4];
                    }
                    __syncwarp();
                    issue_chunk(eb, tstride, sm, lane, buf, k + 2 * CHUNK, K,
                                true, ilen - 1);
                    buf ^= 1;
#pragma unroll
                    for (int j = 0; j < CHUNK; ++j) {
                        if (k <= K) {
                            float e[7] = {E0[j].x, E0[j].y, E0[j].z, E0[j].w,
                                          E1[j].x, E1[j].y, E1[j].z};
                            float h0 = __shfl_down_sync(0xffffffffu, a[0], 1);
                            float h1 = __shfl_down_sync(0xffffffffu, a[1], 1);
                            if (lane == 31) { h0 = NEGV; h1 = NEGV; }
#pragma unroll
                            for (int i = 0; i <= 6; ++i) {
                                float x0 = a[i];
                                float x1 = (i <= 5) ? a[i + 1] : h0;
                                float x2 = (i <= 4) ? a[i + 2] : ((i == 5) ? h0 : h1);
                                x2 = bskip[i] ? x2 : NEGV;
                                a[i] = lae3(x0, x1, x2) + e[i];
                            }
                            ++k;
                        }
                    }
                }
            }
            // gamma: one transition-only step (no emission)
            {
                float h0 = __shfl_down_sync(0xffffffffu, a[0], 1);
                float h1 = __shfl_down_sync(0xffffffffu, a[1], 1);
                if (lane == 31) { h0 = NEGV; h1 = NEGV; }
                float na[7];
#pragma unroll
                for (int i = 0; i <= 6; ++i) {
                    float x0 = a[i];
                    float x1 = (i <= 5) ? a[i + 1] : h0;
                    float x2 = (i <= 4) ? a[i + 2] : ((i == 5) ? h0 : h1);
                    x2 = bskip[i] ? x2 : NEGV;
                    na[i] = lae3(x0, x1, x2);
                }
#pragma unroll
                for (int i = 0; i < 7; ++i) a[i] = na[i];
            }
        }
#pragma unroll
        for (int i = 0; i < 7; ++i)
            g_gamma[n * 224 + 7 * lane + i] = a[i];
    }

    // ---- finisher: last fb block combines, reduces, resets ----
    __threadfence();
    unsigned done = 0;
    if (lane == 0) done = (atomicAdd(&g_fb_ctr, 1u) == (unsigned)(2 * N) - 1u);
    done = __shfl_sync(0xffffffffu, done, 0);
    if (done) {
        __threadfence();
        float acc = 0.0f;
        for (int nn = 0; nn < N; ++nn) {
            float v[7];
            float mx = -3.4e38f;
#pragma unroll
            for (int k = 0; k < 7; ++k) {
                v[k] = g_alpha[nn * 224 + lane + 32 * k]
                     + g_gamma[nn * 224 + lane + 32 * k];
                mx = fmaxf(mx, v[k]);
            }
#pragma unroll
            for (int o = 16; o > 0; o >>= 1)
                mx = fmaxf(mx, __shfl_xor_sync(0xffffffffu, mx, o));
            float sum = 0.0f;
#pragma unroll
            for (int k = 0; k < 7; ++k)
                sum += (v[k] - mx > -120.0f) ? ex2f(v[k] - mx) : 0.0f;
#pragma unroll
            for (int o = 16; o > 0; o >>= 1)
                sum += __shfl_xor_sync(0xffffffffu, sum, o);
            float tot = (mx + lg2f(sum)) * LN2;
            if (lane == 0 && tot > -1e29f) acc += tot;
        }
        if (lane == 0) {
            out[0] = -acc;
            g_fb_ctr = 0u;
            __threadfence();
        }
    }
}

extern "C" void kernel_launch(void* const* d_in, const int* in_sizes, int n_in,
                              void* d_out, int out_size) {
    const float* lp      = (const float*)d_in[0];
    const int*   targets = (const int*)d_in[1];
    const int*   il      = (const int*)d_in[2];
    const int*   tl      = (const int*)d_in[3];

    const int N = in_sizes[2];
    const int L = in_sizes[1] / N;        // 100
    const int C = 1024;                   // fixed for this problem id
    const int T = in_sizes[0] / (N * C);  // 1500
    const int S = 2 * L + 1;              // 201 (needs S <= 217)

    gather_kernel<<<T * N, 256>>>(lp, targets, N, C, L, S);
    fb_kernel<<<2 * N, 32>>>(targets, il, tl, (float*)d_out, N, L);
}

// round 12
// speedup vs baseline: 2.5237x; 1.2006x over previous
#include <cuda_runtime.h>
#include <cstdint>

#define NEGV (-1e30f)
#define LOG2E 1.4426950408889634f
#define LN2   0.6931471805599453f
#define CHUNK 8

// Static device scratch (allocation APIs are forbidden).
__device__ float    g_emit[12u * 1024u * 1024u];  // e[t][n][256], slot = state
__device__ float    g_alpha[1024 * 256];
__device__ float    g_gamma[1024 * 256];
__device__ unsigned g_fb_ctr;                      // zero-init; reset each call

__device__ __forceinline__ float ex2f(float x) {
    float y; asm("ex2.approx.ftz.f32 %0, %1;" : "=f"(y) : "f"(x)); return y;
}
__device__ __forceinline__ float lg2f(float x) {
    float y; asm("lg2.approx.ftz.f32 %0, %1;" : "=f"(y) : "f"(x)); return y;
}
__device__ __forceinline__ float lae3(float x0, float x1, float x2) {
    float hi = fmaxf(x0, fmaxf(x1, x2));
    float lo = fminf(x0, fminf(x1, x2));
    float md = fmaxf(fminf(x0, x1), fminf(fmaxf(x0, x1), x2));
    return hi + lg2f(1.0f + ex2f(md - hi) + ex2f(lo - hi));
}

// ---------------------------------------------------------------------------
// Phase 1: parallel emission gather, direct state layout, log2 domain.
// ---------------------------------------------------------------------------
__global__ void gather_kernel(const float* __restrict__ lp,
                              const int*   __restrict__ targets,
                              int N, int C, int L, int S) {
    const int tn = blockIdx.x;
    const int n  = tn % N;
    const int s  = threadIdx.x;           // slot == state, 0..255
    float e = NEGV;
    if (s < S) {
        int lab = 0;
        if (s & 1) lab = __ldg(&targets[n * L + (s >> 1)]);
        e = __ldg(lp + (size_t)tn * C + lab) * LOG2E;
    }
    g_emit[(size_t)tn * 256 + s] = e;
}

// ---------------------------------------------------------------------------
// Phase 2: fwd+bwd halves. 2 warps per CTA (different SMSPs), 4 states/lane.
// Cross-warp boundary via parity-double-buffered smem + ONE bar.sync per step.
// Emissions per warp through its own cp.async double-buffered FIFO, staged to
// registers a chunk at a time. Last finishing block combines + reduces.
// ---------------------------------------------------------------------------
__device__ __forceinline__ void issue_half(const float* ebase, size_t tstride,
                                           float (*buf)[CHUNK][128], int lane,
                                           int b, int i0, int imax,
                                           bool desc, int tbase) {
#pragma unroll
    for (int j = 0; j < CHUNK; ++j) {
        int ii = i0 + j;
        if (ii > imax) ii = imax;
        int tt = desc ? (tbase - ii) : ii;
        const float* src = ebase + (size_t)tt * tstride;
        uint32_t dst = (uint32_t)__cvta_generic_to_shared(&buf[b][j][lane * 4]);
        asm volatile("cp.async.cg.shared.global [%0], [%1], 16;"
                     :: "r"(dst), "l"(src));
    }
    asm volatile("cp.async.commit_group;" ::: "memory");
}

__global__ void __launch_bounds__(64, 1)
fb_kernel(const int* __restrict__ targets,
          const int* __restrict__ il,
          const int* __restrict__ tl,
          float*     __restrict__ out,
          int N, int L) {
    __shared__ float  sm_e[2][2][CHUNK][128];  // [warp][buf][step][128 states]
    __shared__ float2 halo[2];                 // parity double buffer

    const bool fwd = (blockIdx.x < (unsigned)N);
    const int  n    = fwd ? blockIdx.x : (blockIdx.x - N);
    const int  w    = threadIdx.x >> 5;        // warp0: s 0..127, warp1: 128..255
    const int  lane = threadIdx.x & 31;
    const int  S    = 2 * L + 1;
    const int  base = w * 128 + lane * 4;

    const int ilen  = il[n];
    const int s_end = 2 * tl[n];
    const int m     = (ilen - 1) >> 1;

    const float* ebase   = g_emit + (size_t)n * 256 + base;
    const size_t tstride = (size_t)N * 256;
    float (*buf)[CHUNK][128] = sm_e[w];

    float a[4];

    if (fwd) {
        bool skip[4];
#pragma unroll
        for (int i = 0; i < 4; ++i) {
            int s = base + i;
            skip[i] = false;
            if (s < S && (s & 1) && s >= 3)
                skip[i] = (__ldg(&targets[n * L + (s >> 1)]) !=
                           __ldg(&targets[n * L + (s >> 1) - 1]));
        }
        {   // t = 0
            float4 E = __ldg((const float4*)ebase);
            float e0[4] = {E.x, E.y, E.z, E.w};
#pragma unroll
            for (int i = 0; i < 4; ++i)
                a[i] = (base + i <= 1) ? e0[i] : NEGV;
        }
        if (w == 0 && lane == 31) halo[0] = make_float2(a[2], a[3]); // s126,127
        __syncthreads();

        if (m >= 1) {
            issue_half(ebase, tstride, buf, lane, 0, 1, m, false, 0);
            issue_half(ebase, tstride, buf, lane, 1, 1 + CHUNK, m, false, 0);
            int t = 1, b = 0;
            while (t <= m) {
                asm volatile("cp.async.wait_group 1;" ::: "memory");
                __syncwarp();
                float4 E[CHUNK];
#pragma unroll
                for (int j = 0; j < CHUNK; ++j)
                    E[j] = *(const float4*)&buf[b][j][lane * 4];
                __syncwarp();
                issue_half(ebase, tstride, buf, lane, b, t + 2 * CHUNK, m, false, 0);
                b ^= 1;
#pragma unroll
                for (int j = 0; j < CHUNK; ++j) {
                    if (t <= m) {                      // uniform across CTA
                        float2 h = make_float2(NEGV, NEGV);
                        if (w == 1 && lane == 0) h = halo[(t - 1) & 1];
                        float s3 = __shfl_up_sync(0xffffffffu, a[3], 1);
                        float s2 = __shfl_up_sync(0xffffffffu, a[2], 1);
                        if (lane == 0) { s2 = h.x; s3 = h.y; }
                        float e[4] = {E[j].x, E[j].y, E[j].z, E[j].w};
                        a[3] = lae3(a[3], a[2], skip[3] ? a[1] : NEGV) + e[3];
                        a[2] = lae3(a[2], a[1], skip[2] ? a[0] : NEGV) + e[2];
                        a[1] = lae3(a[1], a[0], skip[1] ? s3   : NEGV) + e[1];
                        a[0] = lae3(a[0], s3,   skip[0] ? s2   : NEGV) + e[0];
                        if (w == 0 && lane == 31)
                            halo[t & 1] = make_float2(a[2], a[3]);
                        __syncthreads();
                        ++t;
                    }
                }
            }
        }
#pragma unroll
        for (int i = 0; i < 4; ++i) g_alpha[n * 256 + base + i] = a[i];
    } else {
        bool bskip[4];
#pragma unroll
        for (int i = 0; i < 4; ++i) {
            int s = base + i;
            bskip[i] = false;
            if (s < S && (s & 1) && (s >> 1) + 1 <= L - 1)
                bskip[i] = (__ldg(&targets[n * L + (s >> 1)]) !=
                            __ldg(&targets[n * L + (s >> 1) + 1]));
        }
        if (ilen == 1) {
#pragma unroll
            for (int i = 0; i < 4; ++i) {
                int s = base + i;
                a[i] = (s == s_end || (s_end >= 1 && s == s_end - 1)) ? 0.0f : NEGV;
            }
        } else {
            {   // init beta at t = ilen-1
                float4 E = __ldg((const float4*)(ebase + (size_t)(ilen - 1) * tstride));
                float e0[4] = {E.x, E.y, E.z, E.w};
#pragma unroll
                for (int i = 0; i < 4; ++i) {
                    int s = base + i;
                    a[i] = (s == s_end || (s_end >= 1 && s == s_end - 1))
                           ? e0[i] : NEGV;
                }
            }
            if (w == 1 && lane == 0) halo[0] = make_float2(a[0], a[1]); // s128,129
            __syncthreads();

            const int K = ilen - 2 - m;
            if (K >= 1) {
                issue_half(ebase, tstride, buf, lane, 0, 1, K, true, ilen - 1);
                issue_half(ebase, tstride, buf, lane, 1, 1 + CHUNK, K, true, ilen - 1);
                int k = 1, b = 0;
                while (k <= K) {
                    asm volatile("cp.async.wait_group 1;" ::: "memory");
                    __syncwarp();
                    float4 E[CHUNK];
#pragma unroll
                    for (int j = 0; j < CHUNK; ++j)
                        E[j] = *(const float4*)&buf[b][j][lane * 4];
                    __syncwarp();
                    issue_half(ebase, tstride, buf, lane, b, k + 2 * CHUNK, K,
                               true, ilen - 1);
                    b ^= 1;
#pragma unroll
                    for (int j = 0; j < CHUNK; ++j) {
                        if (k <= K) {                  // uniform across CTA
                            float2 h = make_float2(NEGV, NEGV);
                            if (w == 0 && lane == 31) h = halo[(k - 1) & 1];
                            float d0 = __shfl_down_sync(0xffffffffu, a[0], 1);
                            float d1 = __shfl_down_sync(0xffffffffu, a[1], 1);
                            if (lane == 31) { d0 = h.x; d1 = h.y; }
                            float e[4] = {E[j].x, E[j].y, E[j].z, E[j].w};
                            a[0] = lae3(a[0], a[1], bskip[0] ? a[2] : NEGV) + e[0];
                            a[1] = lae3(a[1], a[2], bskip[1] ? a[3] : NEGV) + e[1];
                            a[2] = lae3(a[2], a[3], bskip[2] ? d0   : NEGV) + e[2];
                            a[3] = lae3(a[3], d0,   bskip[3] ? d1   : NEGV) + e[3];
                            if (w == 1 && lane == 0)
                                halo[k & 1] = make_float2(a[0], a[1]);
                            __syncthreads();
                            ++k;
                        }
                    }
                }
            }
            {   // gamma: one transition-only step (no emission, no barrier)
                float2 h = make_float2(NEGV, NEGV);
                if (w == 0 && lane == 31) h = halo[(K >= 1 ? K : 0) & 1];
                float d0 = __shfl_down_sync(0xffffffffu, a[0], 1);
                float d1 = __shfl_down_sync(0xffffffffu, a[1], 1);
                if (lane == 31) { d0 = h.x; d1 = h.y; }
                a[0] = lae3(a[0], a[1], bskip[0] ? a[2] : NEGV);
                a[1] = lae3(a[1], a[2], bskip[1] ? a[3] : NEGV);
                a[2] = lae3(a[2], a[3], bskip[2] ? d0   : NEGV);
                a[3] = lae3(a[3], d0,   bskip[3] ? d1   : NEGV);
            }
        }
#pragma unroll
        for (int i = 0; i < 4; ++i) g_gamma[n * 256 + base + i] = a[i];
    }

    // ---- finisher: last block combines (per-n logsumexp) + fixed-order sum ----
    __threadfence();
    unsigned done = 0;
    if (threadIdx.x == 0)
        done = (atomicAdd(&g_fb_ctr, 1u) == (unsigned)(2 * N) - 1u);
    done = __shfl_sync(0xffffffffu, done, 0);
    if (w == 0 && done) {
        __threadfence();
        float acc = 0.0f;
        for (int nn = 0; nn < N; ++nn) {
            float v[8];
            float mx = -3.4e38f;
#pragma unroll
            for (int k = 0; k < 8; ++k) {
                v[k] = g_alpha[nn * 256 + lane + 32 * k]
                     + g_gamma[nn * 256 + lane + 32 * k];
                mx = fmaxf(mx, v[k]);
            }
#pragma unroll
            for (int o = 16; o > 0; o >>= 1)
                mx = fmaxf(mx, __shfl_xor_sync(0xffffffffu, mx, o));
            float sum = 0.0f;
#pragma unroll
            for (int k = 0; k < 8; ++k)
                sum += (v[k] - mx > -120.0f) ? ex2f(v[k] - mx) : 0.0f;
#pragma unroll
            for (int o = 16; o > 0; o >>= 1)
                sum += __shfl_xor_sync(0xffffffffu, sum, o);
            float tot = (mx + lg2f(sum)) * LN2;
            if (lane == 0 && tot > -1e29f) acc += tot;
        }
        if (lane == 0) {
            out[0] = -acc;
            g_fb_ctr = 0u;
            __threadfence();
        }
    }
}

extern "C" void kernel_launch(void* const* d_in, const int* in_sizes, int n_in,
                              void* d_out, int out_size) {
    const float* lp      = (const float*)d_in[0];
    const int*   targets = (const int*)d_in[1];
    const int*   il      = (const int*)d_in[2];
    const int*   tl      = (const int*)d_in[3];

    const int N = in_sizes[2];
    const int L = in_sizes[1] / N;        // 100
    const int C = 1024;                   // fixed for this problem id
    const int T = in_sizes[0] / (N * C);  // 1500
    const int S = 2 * L + 1;              // 201 (needs S <= 256)

    gather_kernel<<<T * N, 256>>>(lp, targets, N, C, L, S);
    fb_kernel<<<2 * N, 64>>>(targets, il, tl, (float*)d_out, N, L);
}

// round 13
// speedup vs baseline: 2.7797x; 1.1014x over previous
#include <cuda_runtime.h>
#include <cstdint>

#define NEGV (-1e30f)
#define LOG2E 1.4426950408889634f
#define LN2   0.6931471805599453f
#define CHUNK 8

// Static device scratch (allocation APIs are forbidden).
__device__ float    g_emit[12u * 1024u * 1024u];  // e[t][n][256], slot = state
__device__ float    g_alpha[1024 * 256];
__device__ float    g_gamma[1024 * 256];
__device__ unsigned g_fb_ctr;                      // zero-init; reset each call

__device__ __forceinline__ float ex2f(float x) {
    float y; asm("ex2.approx.ftz.f32 %0, %1;" : "=f"(y) : "f"(x)); return y;
}
__device__ __forceinline__ float lg2f(float x) {
    float y; asm("lg2.approx.ftz.f32 %0, %1;" : "=f"(y) : "f"(x)); return y;
}
__device__ __forceinline__ float lae3(float x0, float x1, float x2) {
    float hi = fmaxf(x0, fmaxf(x1, x2));
    float lo = fminf(x0, fminf(x1, x2));
    float md = fmaxf(fminf(x0, x1), fminf(fmaxf(x0, x1), x2));
    return hi + lg2f(1.0f + ex2f(md - hi) + ex2f(lo - hi));
}

// ---------------------------------------------------------------------------
// Phase 1: parallel emission gather, direct state layout, log2 domain.
// ---------------------------------------------------------------------------
__global__ void gather_kernel(const float* __restrict__ lp,
                              const int*   __restrict__ targets,
                              int N, int C, int L, int S) {
    const int tn = blockIdx.x;
    const int n  = tn % N;
    const int s  = threadIdx.x;           // slot == state, 0..255
    float e = NEGV;
    if (s < S) {
        int lab = 0;
        if (s & 1) lab = __ldg(&targets[n * L + (s >> 1)]);
        e = __ldg(lp + (size_t)tn * C + lab) * LOG2E;
    }
    g_emit[(size_t)tn * 256 + s] = e;
}

// ---------------------------------------------------------------------------
// Phase 2: fwd+bwd halves. 2 warps per CTA with OVERLAPPING state ranges
// (halo-recompute): zero per-step sync; one smem exchange per 8-step chunk.
//   fwd: w0 owns 0..127 (self-sufficient), w1 covers 112..239; states
//        112..127 are w1's recompute zone, refreshed from w0 each chunk.
//   bwd: w1 covers 80..207 (self-sufficient), w0 covers 0..127 with zone
//        112..127 refreshed from w1 each chunk (+once more before gamma).
// Garbage from the zone edge moves 2 states/step; 8 steps * 2 = 16 = zone
// width, so owned states stay exact.
// ---------------------------------------------------------------------------
__device__ __forceinline__ void issue_half(const float* ebase, size_t tstride,
                                           float (*buf)[CHUNK][128], int lane,
                                           int b, int i0, int imax,
                                           bool desc, int tbase) {
#pragma unroll
    for (int j = 0; j < CHUNK; ++j) {
        int ii = i0 + j;
        if (ii > imax) ii = imax;
        int tt = desc ? (tbase - ii) : ii;
        const float* src = ebase + (size_t)tt * tstride;
        uint32_t dst = (uint32_t)__cvta_generic_to_shared(&buf[b][j][lane * 4]);
        asm volatile("cp.async.cg.shared.global [%0], [%1], 16;"
                     :: "r"(dst), "l"(src));
    }
    asm volatile("cp.async.commit_group;" ::: "memory");
}

__global__ void __launch_bounds__(64, 1)
fb_kernel(const int* __restrict__ targets,
          const int* __restrict__ il,
          const int* __restrict__ tl,
          float*     __restrict__ out,
          int N, int L) {
    __shared__ float sm_e[2][2][CHUNK][128];  // [warp][buf][step][128 slots]
    __shared__ float xfer[2][16];             // zone exchange, parity buffered

    const bool fwd = (blockIdx.x < (unsigned)N);
    const int  n    = fwd ? blockIdx.x : (blockIdx.x - N);
    const int  w    = threadIdx.x >> 5;
    const int  lane = threadIdx.x & 31;
    const int  S    = 2 * L + 1;

    const int ilen  = il[n];
    const int s_end = 2 * tl[n];
    const int m     = (ilen - 1) >> 1;

    // State range per role.
    const int base = fwd ? (w == 0 ? lane * 4 : 112 + lane * 4)
                         : (w == 0 ? lane * 4 : 80  + lane * 4);

    const float* ebase   = g_emit + (size_t)n * 256 + base;
    const size_t tstride = (size_t)N * 256;
    float (*buf)[CHUNK][128] = sm_e[w];

    float a[4];

    if (fwd) {
        bool skip[4];
#pragma unroll
        for (int i = 0; i < 4; ++i) {
            int s = base + i;
            skip[i] = false;
            if (s < S && (s & 1) && s >= 3)
                skip[i] = (__ldg(&targets[n * L + (s >> 1)]) !=
                           __ldg(&targets[n * L + (s >> 1) - 1]));
        }
        {   // t = 0
            float4 E = __ldg((const float4*)ebase);
            float e0[4] = {E.x, E.y, E.z, E.w};
#pragma unroll
            for (int i = 0; i < 4; ++i)
                a[i] = (base + i <= 1) ? e0[i] : NEGV;
        }

        if (m >= 1) {
            issue_half(ebase, tstride, buf, lane, 0, 1, m, false, 0);
            issue_half(ebase, tstride, buf, lane, 1, 1 + CHUNK, m, false, 0);
            int t = 1, b = 0, xb = 0;
            while (t <= m) {
                // ---- zone exchange: w0 states 112..127 -> w1 ----
                xb ^= 1;
                if (w == 0 && lane >= 28) {
                    int o = (lane - 28) * 4;
#pragma unroll
                    for (int i = 0; i < 4; ++i) xfer[xb][o + i] = a[i];
                }
                __syncthreads();
                if (w == 1 && lane < 4) {
#pragma unroll
                    for (int i = 0; i < 4; ++i) a[i] = xfer[xb][lane * 4 + i];
                }

                asm volatile("cp.async.wait_group 1;" ::: "memory");
                __syncwarp();
                float4 E[CHUNK];
#pragma unroll
                for (int j = 0; j < CHUNK; ++j)
                    E[j] = *(const float4*)&buf[b][j][lane * 4];
                __syncwarp();
                issue_half(ebase, tstride, buf, lane, b, t + 2 * CHUNK, m, false, 0);
                b ^= 1;
#pragma unroll
                for (int j = 0; j < CHUNK; ++j) {
                    if (t <= m) {
                        float s3 = __shfl_up_sync(0xffffffffu, a[3], 1);
                        float s2 = __shfl_up_sync(0xffffffffu, a[2], 1);
                        if (lane == 0) { s2 = NEGV; s3 = NEGV; }  // both warps
                        float e[4] = {E[j].x, E[j].y, E[j].z, E[j].w};
                        a[3] = lae3(a[3], a[2], skip[3] ? a[1] : NEGV) + e[3];
                        a[2] = lae3(a[2], a[1], skip[2] ? a[0] : NEGV) + e[2];
                        a[1] = lae3(a[1], a[0], skip[1] ? s3   : NEGV) + e[1];
                        a[0] = lae3(a[0], s3,   skip[0] ? s2   : NEGV) + e[0];
                        ++t;
                    }
                }
            }
        }
        // authoritative split: w0 -> 0..127, w1 (lane>=4) -> 128..239
        if (w == 0) {
#pragma unroll
            for (int i = 0; i < 4; ++i) g_alpha[n * 256 + base + i] = a[i];
        } else if (lane >= 4) {
#pragma unroll
            for (int i = 0; i < 4; ++i) g_alpha[n * 256 + base + i] = a[i];
        }
        if (w == 1 && lane < 4) {       // pad 240..255
#pragma unroll
            for (int i = 0; i < 4; ++i) g_alpha[n * 256 + 240 + lane * 4 + i] = NEGV;
        }
    } else {
        bool bskip[4];
#pragma unroll
        for (int i = 0; i < 4; ++i) {
            int s = base + i;
            bskip[i] = false;
            if (s < S && (s & 1) && (s >> 1) + 1 <= L - 1)
                bskip[i] = (__ldg(&targets[n * L + (s >> 1)]) !=
                            __ldg(&targets[n * L + (s >> 1) + 1]));
        }
        if (ilen == 1) {
#pragma unroll
            for (int i = 0; i < 4; ++i) {
                int s = base + i;
                a[i] = (s == s_end || (s_end >= 1 && s == s_end - 1)) ? 0.0f : NEGV;
            }
        } else {
            {   // init beta at t = ilen-1
                float4 E = __ldg((const float4*)(ebase + (size_t)(ilen - 1) * tstride));
                float e0[4] = {E.x, E.y, E.z, E.w};
#pragma unroll
                for (int i = 0; i < 4; ++i) {
                    int s = base + i;
                    a[i] = (s == s_end || (s_end >= 1 && s == s_end - 1))
                           ? e0[i] : NEGV;
                }
            }
            const int K = ilen - 2 - m;
            int xb = 0;
            if (K >= 1) {
                issue_half(ebase, tstride, buf, lane, 0, 1, K, true, ilen - 1);
                issue_half(ebase, tstride, buf, lane, 1, 1 + CHUNK, K, true, ilen - 1);
                int k = 1, b = 0;
                while (k <= K) {
                    // ---- zone exchange: w1 states 112..127 -> w0 ----
                    xb ^= 1;
                    if (w == 1 && lane >= 8 && lane < 12) {
                        int o = (lane - 8) * 4;
#pragma unroll
                        for (int i = 0; i < 4; ++i) xfer[xb][o + i] = a[i];
                    }
                    __syncthreads();
                    if (w == 0 && lane >= 28) {
#pragma unroll
                        for (int i = 0; i < 4; ++i)
                            a[i] = xfer[xb][(lane - 28) * 4 + i];
                    }

                    asm volatile("cp.async.wait_group 1;" ::: "memory");
                    __syncwarp();
                    float4 E[CHUNK];
#pragma unroll
                    for (int j = 0; j < CHUNK; ++j)
                        E[j] = *(const float4*)&buf[b][j][lane * 4];
                    __syncwarp();
                    issue_half(ebase, tstride, buf, lane, b, k + 2 * CHUNK, K,
                               true, ilen - 1);
                    b ^= 1;
#pragma unroll
                    for (int j = 0; j < CHUNK; ++j) {
                        if (k <= K) {
                            float d0 = __shfl_down_sync(0xffffffffu, a[0], 1);
                            float d1 = __shfl_down_sync(0xffffffffu, a[1], 1);
                            if (lane == 31) { d0 = NEGV; d1 = NEGV; }  // both
                            float e[4] = {E[j].x, E[j].y, E[j].z, E[j].w};
                            a[0] = lae3(a[0], a[1], bskip[0] ? a[2] : NEGV) + e[0];
                            a[1] = lae3(a[1], a[2], bskip[1] ? a[3] : NEGV) + e[1];
                            a[2] = lae3(a[2], a[3], bskip[2] ? d0   : NEGV) + e[2];
                            a[3] = lae3(a[3], d0,   bskip[3] ? d1   : NEGV) + e[3];
                            ++k;
                        }
                    }
                }
            }
            // ---- final zone exchange before gamma ----
            xb ^= 1;
            if (w == 1 && lane >= 8 && lane < 12) {
                int o = (lane - 8) * 4;
#pragma unroll
                for (int i = 0; i < 4; ++i) xfer[xb][o + i] = a[i];
            }
            __syncthreads();
            if (w == 0 && lane >= 28) {
#pragma unroll
                for (int i = 0; i < 4; ++i) a[i] = xfer[xb][(lane - 28) * 4 + i];
            }
            {   // gamma: one transition-only step (no emission)
                float d0 = __shfl_down_sync(0xffffffffu, a[0], 1);
                float d1 = __shfl_down_sync(0xffffffffu, a[1], 1);
                if (lane == 31) { d0 = NEGV; d1 = NEGV; }
                a[0] = lae3(a[0], a[1], bskip[0] ? a[2] : NEGV);
                a[1] = lae3(a[1], a[2], bskip[1] ? a[3] : NEGV);
                a[2] = lae3(a[2], a[3], bskip[2] ? d0   : NEGV);
                a[3] = lae3(a[3], d0,   bskip[3] ? d1   : NEGV);
            }
        }
        // authoritative split: w0 (lane<28) -> 0..111, w1 (lane>=8) -> 112..207
        if (w == 0 && lane < 28) {
#pragma unroll
            for (int i = 0; i < 4; ++i) g_gamma[n * 256 + base + i] = a[i];
        } else if (w == 1 && lane >= 8) {
#pragma unroll
            for (int i = 0; i < 4; ++i) g_gamma[n * 256 + base + i] = a[i];
        }
        if (w == 0 && lane >= 28) {     // pad 208..223
#pragma unroll
            for (int i = 0; i < 4; ++i)
                g_gamma[n * 256 + 208 + (lane - 28) * 4 + i] = NEGV;
        }
        if (w == 1 && lane < 8) {       // pad 224..255
#pragma unroll
            for (int i = 0; i < 4; ++i)
                g_gamma[n * 256 + 224 + lane * 4 + i] = NEGV;
        }
    }

    // ---- finisher: last block combines (per-n logsumexp) + fixed-order sum ----
    __threadfence();
    unsigned done = 0;
    if (threadIdx.x == 0)
        done = (atomicAdd(&g_fb_ctr, 1u) == (unsigned)(2 * N) - 1u);
    done = __shfl_sync(0xffffffffu, done, 0);
    if (w == 0 && done) {
        __threadfence();
        float acc = 0.0f;
        for (int nn = 0; nn < N; ++nn) {
            float v[8];
            float mx = -3.4e38f;
#pragma unroll
            for (int k = 0; k < 8; ++k) {
                v[k] = g_alpha[nn * 256 + lane + 32 * k]
                     + g_gamma[nn * 256 + lane + 32 * k];
                mx = fmaxf(mx, v[k]);
            }
#pragma unroll
            for (int o = 16; o > 0; o >>= 1)
                mx = fmaxf(mx, __shfl_xor_sync(0xffffffffu, mx, o));
            float sum = 0.0f;
#pragma unroll
            for (int k = 0; k < 8; ++k)
                sum += (v[k] - mx > -120.0f) ? ex2f(v[k] - mx) : 0.0f;
#pragma unroll
            for (int o = 16; o > 0; o >>= 1)
                sum += __shfl_xor_sync(0xffffffffu, sum, o);
            float tot = (mx + lg2f(sum)) * LN2;
            if (lane == 0 && tot > -1e29f) acc += tot;
        }
        if (lane == 0) {
            out[0] = -acc;
            g_fb_ctr = 0u;
            __threadfence();
        }
    }
}

extern "C" void kernel_launch(void* const* d_in, const int* in_sizes, int n_in,
                              void* d_out, int out_size) {
    const float* lp      = (const float*)d_in[0];
    const int*   targets = (const int*)d_in[1];
    const int*   il      = (const int*)d_in[2];
    const int*   tl      = (const int*)d_in[3];

    const int N = in_sizes[2];
    const int L = in_sizes[1] / N;        // 100
    const int C = 1024;                   // fixed for this problem id
    const int T = in_sizes[0] / (N * C);  // 1500
    const int S = 2 * L + 1;              // 201 (needs S <= 207 for bwd split)

    gather_kernel<<<T * N, 256>>>(lp, targets, N, C, L, S);
    fb_kernel<<<2 * N, 64>>>(targets, il, tl, (float*)d_out, N, L);
}

// round 14
// speedup vs baseline: 3.1497x; 1.1331x over previous
#include <cuda_runtime.h>
#include <cstdint>

#define NEGV (-1e30f)
#define LOG2E 1.4426950408889634f
#define LN2   0.6931471805599453f
#define CHUNK 8
#define TT    64            // t-tile per gather block

// Static device scratch (allocation APIs are forbidden).
__device__ float    g_emit[12u * 1024u * 1024u];  // e[t][n][256], slot = state
__device__ float    g_alpha[1024 * 256];
__device__ float    g_gamma[1024 * 256];
__device__ unsigned g_fb_ctr;                      // zero-init; reset each call

__device__ __forceinline__ float ex2f(float x) {
    float y; asm("ex2.approx.ftz.f32 %0, %1;" : "=f"(y) : "f"(x)); return y;
}
__device__ __forceinline__ float lg2f(float x) {
    float y; asm("lg2.approx.ftz.f32 %0, %1;" : "=f"(y) : "f"(x)); return y;
}
__device__ __forceinline__ float lae3(float x0, float x1, float x2) {
    float hi = fmaxf(x0, fmaxf(x1, x2));
    float lo = fminf(x0, fminf(x1, x2));
    float md = fmaxf(fminf(x0, x1), fminf(fmaxf(x0, x1), x2));
    return hi + lg2f(1.0f + ex2f(md - hi) + ex2f(lo - hi));
}

// ---------------------------------------------------------------------------
// Phase 1: emission gather. block = (t-tile, n); label resolved once per
// thread, then 64 t's streamed with an 8-deep MLP ring.
// ---------------------------------------------------------------------------
__global__ void gather_kernel(const float* __restrict__ lp,
                              const int*   __restrict__ targets,
                              int N, int C, int L, int S, int T) {
    const int n  = blockIdx.y;
    const int t0 = blockIdx.x * TT;
    const int s  = threadIdx.x;           // slot == state, 0..255

    const bool valid = (s < S);
    int lab = 0;
    if (valid && (s & 1)) lab = __ldg(&targets[n * L + (s >> 1)]);
    const float* src = lp + (size_t)n * C + lab;
    const size_t lstride = (size_t)N * C;

    for (int u = 0; u < TT; u += 8) {
        float v[8];
#pragma unroll
        for (int j = 0; j < 8; ++j) {
            int tt = t0 + u + j;
            v[j] = (valid && tt < T) ? __ldg(src + (size_t)tt * lstride) * LOG2E
                                     : NEGV;
        }
#pragma unroll
        for (int j = 0; j < 8; ++j) {
            int tt = t0 + u + j;
            if (tt < T) g_emit[((size_t)tt * N + n) * 256 + s] = v[j];
        }
    }
}

// ---------------------------------------------------------------------------
// Phase 2: fwd+bwd halves, FOUR warps per CTA with overlapping coverage
// (halo-recompute), 2 states per lane. Warp w covers slots [48w, 48w+64).
//   fwd owns: w0: 0..63, w1..w3: [48w+16, 48w+64)   (left 16 = zone)
//   bwd owns: w0..w2: [48w, 48w+48), w3: 144..207   (right 16 = zone)
// Zones refreshed once per 8-step chunk (3 smem regions, parity buffered,
// ONE __syncthreads per chunk). Garbage moves 2 slots/step; 8*2=16=zone.
// ---------------------------------------------------------------------------
__device__ __forceinline__ void issue_q(const float* ecov, size_t tstride,
                                        float (*buf)[CHUNK][64], int lane,
                                        int b, int i0, int imax,
                                        bool desc, int tbase) {
    if (lane < 16) {
#pragma unroll
        for (int j = 0; j < CHUNK; ++j) {
            int ii = i0 + j;
            if (ii > imax) ii = imax;
            int tt = desc ? (tbase - ii) : ii;
            const float* src = ecov + (size_t)tt * tstride + lane * 4;
            uint32_t dst = (uint32_t)__cvta_generic_to_shared(&buf[b][j][lane * 4]);
            asm volatile("cp.async.cg.shared.global [%0], [%1], 16;"
                         :: "r"(dst), "l"(src));
        }
    }
    asm volatile("cp.async.commit_group;" ::: "memory");
}

__global__ void __launch_bounds__(128, 1)
fb_kernel(const int* __restrict__ targets,
          const int* __restrict__ il,
          const int* __restrict__ tl,
          float*     __restrict__ out,
          int N, int L) {
    __shared__ float sm_e[4][2][CHUNK][64];   // per-warp emission FIFO
    __shared__ float xfer[2][3][16];          // 3 zone regions, parity buffered

    const bool fwd = (blockIdx.x < (unsigned)N);
    const int  n    = fwd ? blockIdx.x : (blockIdx.x - N);
    const int  w    = threadIdx.x >> 5;
    const int  lane = threadIdx.x & 31;
    const int  S    = 2 * L + 1;

    const int ilen  = il[n];
    const int s_end = 2 * tl[n];
    const int m     = (ilen - 1) >> 1;

    const int covw = 48 * w;
    const int base = covw + lane * 2;

    const float* ecov    = g_emit + (size_t)n * 256 + covw;
    const float* ebase   = g_emit + (size_t)n * 256 + base;
    const size_t tstride = (size_t)N * 256;
    float (*buf)[CHUNK][64] = sm_e[w];

    float a[2];

    if (fwd) {
        bool skip[2];
#pragma unroll
        for (int i = 0; i < 2; ++i) {
            int s = base + i;
            skip[i] = false;
            if (s < S && (s & 1) && s >= 3)
                skip[i] = (__ldg(&targets[n * L + (s >> 1)]) !=
                           __ldg(&targets[n * L + (s >> 1) - 1]));
        }
        {   // t = 0
            float2 E = __ldg((const float2*)ebase);
            a[0] = (base     <= 1) ? E.x : NEGV;
            a[1] = (base + 1 <= 1) ? E.y : NEGV;
        }

        if (m >= 1) {
            issue_q(ecov, tstride, buf, lane, 0, 1, m, false, 0);
            issue_q(ecov, tstride, buf, lane, 1, 1 + CHUNK, m, false, 0);
            int t = 1, b = 0, xb = 0;
            while (t <= m) {
                // zone exchange: w sends slots 48w+48..63 -> w+1 zone
                xb ^= 1;
                if (w < 3 && lane >= 24) {
                    xfer[xb][w][(lane - 24) * 2]     = a[0];
                    xfer[xb][w][(lane - 24) * 2 + 1] = a[1];
                }
                __syncthreads();
                if (w > 0 && lane < 8) {
                    a[0] = xfer[xb][w - 1][lane * 2];
                    a[1] = xfer[xb][w - 1][lane * 2 + 1];
                }

                asm volatile("cp.async.wait_group 1;" ::: "memory");
                __syncwarp();
                float2 E[CHUNK];
#pragma unroll
                for (int j = 0; j < CHUNK; ++j)
                    E[j] = *(const float2*)&buf[b][j][lane * 2];
                __syncwarp();
                issue_q(ecov, tstride, buf, lane, b, t + 2 * CHUNK, m, false, 0);
                b ^= 1;
#pragma unroll
                for (int j = 0; j < CHUNK; ++j) {
                    if (t <= m) {
                        float s1 = __shfl_up_sync(0xffffffffu, a[1], 1); // base-1
                        float s0 = __shfl_up_sync(0xffffffffu, a[0], 1); // base-2
                        if (lane == 0) { s1 = NEGV; s0 = NEGV; }
                        a[1] = lae3(a[1], a[0], skip[1] ? s1 : NEGV) + E[j].y;
                        a[0] = lae3(a[0], s1,   skip[0] ? s0 : NEGV) + E[j].x;
                        ++t;
                    }
                }
            }
        }
        // authoritative: w0 all, w>0 lanes >= 8
        if (w == 0 || lane >= 8) {
            g_alpha[n * 256 + base]     = a[0];
            g_alpha[n * 256 + base + 1] = a[1];
        }
        if (w >= 1 && lane < 8) {          // pad 208..255
            int p = 208 + (w - 1) * 16 + lane * 2;
            g_alpha[n * 256 + p]     = NEGV;
            g_alpha[n * 256 + p + 1] = NEGV;
        }
    } else {
        bool bskip[2];
#pragma unroll
        for (int i = 0; i < 2; ++i) {
            int s = base + i;
            bskip[i] = false;
            if (s < S && (s & 1) && (s >> 1) + 1 <= L - 1)
                bskip[i] = (__ldg(&targets[n * L + (s >> 1)]) !=
                            __ldg(&targets[n * L + (s >> 1) + 1]));
        }
        if (ilen == 1) {
#pragma unroll
            for (int i = 0; i < 2; ++i) {
                int s = base + i;
                a[i] = (s == s_end || (s_end >= 1 && s == s_end - 1)) ? 0.0f : NEGV;
            }
        } else {
            {   // init beta at t = ilen-1
                float2 E = __ldg((const float2*)(ebase + (size_t)(ilen - 1) * tstride));
                float e0[2] = {E.x, E.y};
#pragma unroll
                for (int i = 0; i < 2; ++i) {
                    int s = base + i;
                    a[i] = (s == s_end || (s_end >= 1 && s == s_end - 1))
                           ? e0[i] : NEGV;
                }
            }
            const int K = ilen - 2 - m;
            int xb = 0;
            if (K >= 1) {
                issue_q(ecov, tstride, buf, lane, 0, 1, K, true, ilen - 1);
                issue_q(ecov, tstride, buf, lane, 1, 1 + CHUNK, K, true, ilen - 1);
                int k = 1, b = 0;
                while (k <= K) {
                    // zone exchange: w (>=1) sends its left 16 -> w-1 zone
                    xb ^= 1;
                    if (w >= 1 && lane < 8) {
                        xfer[xb][w - 1][lane * 2]     = a[0];
                        xfer[xb][w - 1][lane * 2 + 1] = a[1];
                    }
                    __syncthreads();
                    if (w < 3 && lane >= 24) {
                        a[0] = xfer[xb][w][(lane - 24) * 2];
                        a[1] = xfer[xb][w][(lane - 24) * 2 + 1];
                    }

                    asm volatile("cp.async.wait_group 1;" ::: "memory");
                    __syncwarp();
                    float2 E[CHUNK];
#pragma unroll
                    for (int j = 0; j < CHUNK; ++j)
                        E[j] = *(const float2*)&buf[b][j][lane * 2];
                    __syncwarp();
                    issue_q(ecov, tstride, buf, lane, b, k + 2 * CHUNK, K,
                            true, ilen - 1);
                    b ^= 1;
#pragma unroll
                    for (int j = 0; j < CHUNK; ++j) {
                        if (k <= K) {
                            float d0 = __shfl_down_sync(0xffffffffu, a[0], 1); // base+2
                            float d1 = __shfl_down_sync(0xffffffffu, a[1], 1); // base+3
                            if (lane == 31) { d0 = NEGV; d1 = NEGV; }
                            a[0] = lae3(a[0], a[1], bskip[0] ? d0 : NEGV) + E[j].x;
                            a[1] = lae3(a[1], d0,   bskip[1] ? d1 : NEGV) + E[j].y;
                            ++k;
                        }
                    }
                }
            }
            // final zone exchange before gamma
            xb ^= 1;
            if (w >= 1 && lane < 8) {
                xfer[xb][w - 1][lane * 2]     = a[0];
                xfer[xb][w - 1][lane * 2 + 1] = a[1];
            }
            __syncthreads();
            if (w < 3 && lane >= 24) {
                a[0] = xfer[xb][w][(lane - 24) * 2];
                a[1] = xfer[xb][w][(lane - 24) * 2 + 1];
            }
            {   // gamma: one transition-only step
                float d0 = __shfl_down_sync(0xffffffffu, a[0], 1);
                float d1 = __shfl_down_sync(0xffffffffu, a[1], 1);
                if (lane == 31) { d0 = NEGV; d1 = NEGV; }
                a[0] = lae3(a[0], a[1], bskip[0] ? d0 : NEGV);
                a[1] = lae3(a[1], d0,   bskip[1] ? d1 : NEGV);
            }
        }
        // authoritative: w3 all, w<3 lanes < 24
        if (w == 3 || lane < 24) {
            g_gamma[n * 256 + base]     = a[0];
            g_gamma[n * 256 + base + 1] = a[1];
        }
        if (w < 3 && lane >= 24) {         // pad 208..255
            int p = 208 + w * 16 + (lane - 24) * 2;
            g_gamma[n * 256 + p]     = NEGV;
            g_gamma[n * 256 + p + 1] = NEGV;
        }
    }

    // ---- finisher: last block combines (per-n logsumexp) + fixed-order sum ----
    __threadfence();
    unsigned done = 0;
    if (threadIdx.x == 0)
        done = (atomicAdd(&g_fb_ctr, 1u) == (unsigned)(2 * N) - 1u);
    done = __shfl_sync(0xffffffffu, done, 0);
    if (w == 0 && done) {
        __threadfence();
        float acc = 0.0f;
        for (int nn = 0; nn < N; ++nn) {
            float v[8];
            float mx = -3.4e38f;
#pragma unroll
            for (int k = 0; k < 8; ++k) {
                v[k] = g_alpha[nn * 256 + lane + 32 * k]
                     + g_gamma[nn * 256 + lane + 32 * k];
                mx = fmaxf(mx, v[k]);
            }
#pragma unroll
            for (int o = 16; o > 0; o >>= 1)
                mx = fmaxf(mx, __shfl_xor_sync(0xffffffffu, mx, o));
            float sum = 0.0f;
#pragma unroll
            for (int k = 0; k < 8; ++k)
                sum += (v[k] - mx > -120.0f) ? ex2f(v[k] - mx) : 0.0f;
#pragma unroll
            for (int o = 16; o > 0; o >>= 1)
                sum += __shfl_xor_sync(0xffffffffu, sum, o);
            float tot = (mx + lg2f(sum)) * LN2;
            if (lane == 0 && tot > -1e29f) acc += tot;
        }
        if (lane == 0) {
            out[0] = -acc;
            g_fb_ctr = 0u;
            __threadfence();
        }
    }
}

extern "C" void kernel_launch(void* const* d_in, const int* in_sizes, int n_in,
                              void* d_out, int out_size) {
    const float* lp      = (const float*)d_in[0];
    const int*   targets = (const int*)d_in[1];
    const int*   il      = (const int*)d_in[2];
    const int*   tl      = (const int*)d_in[3];

    const int N = in_sizes[2];
    const int L = in_sizes[1] / N;        // 100
    const int C = 1024;                   // fixed for this problem id
    const int T = in_sizes[0] / (N * C);  // 1500
    const int S = 2 * L + 1;              // 201 (needs S <= 208)

    dim3 ggrid((T + TT - 1) / TT, N);
    gather_kernel<<<ggrid, 256>>>(lp, targets, N, C, L, S, T);
    fb_kernel<<<2 * N, 128>>>(targets, il, tl, (float*)d_out, N, L);
}

// round 15
// speedup vs baseline: 3.4339x; 1.0902x over previous
#include <cuda_runtime.h>
#include <cstdint>

#define NEGV (-1e30f)
#define LOG2E 1.4426950408889634f
#define LN2   0.6931471805599453f
#define CHUNK 8
#define TT    64            // t-tile per gather block

// Static device scratch (allocation APIs are forbidden).
__device__ float    g_emit[12u * 1024u * 1024u];  // e[t][n][256], slot = state
__device__ float    g_alpha[1024 * 256];
__device__ float    g_gamma[1024 * 256];
__device__ unsigned g_fb_ctr;                      // zero-init; reset each call

__device__ __forceinline__ float ex2f(float x) {
    float y; asm("ex2.approx.ftz.f32 %0, %1;" : "=f"(y) : "f"(x)); return y;
}
__device__ __forceinline__ float lg2f(float x) {
    float y; asm("lg2.approx.ftz.f32 %0, %1;" : "=f"(y) : "f"(x)); return y;
}
// x2 is the late-arriving operand (shfl) -> keep it shallow in the trees.
__device__ __forceinline__ float lae3(float x0, float x1, float x2) {
    float m01 = fmaxf(x0, x1), n01 = fminf(x0, x1);
    float hi  = fmaxf(m01, x2);
    float lo  = fminf(n01, x2);
    float md  = fmaxf(n01, fminf(m01, x2));
    return hi + lg2f(1.0f + ex2f(md - hi) + ex2f(lo - hi));
}

// ---------------------------------------------------------------------------
// Phase 1: emission gather. block = (t-tile, n); label resolved once per
// thread, then 64 t's streamed with an 8-deep MLP ring.
// ---------------------------------------------------------------------------
__global__ void gather_kernel(const float* __restrict__ lp,
                              const int*   __restrict__ targets,
                              int N, int C, int L, int S, int T) {
    const int n  = blockIdx.y;
    const int t0 = blockIdx.x * TT;
    const int s  = threadIdx.x;           // slot == state, 0..255

    const bool valid = (s < S);
    int lab = 0;
    if (valid && (s & 1)) lab = __ldg(&targets[n * L + (s >> 1)]);
    const float* src = lp + (size_t)n * C + lab;
    const size_t lstride = (size_t)N * C;

    for (int u = 0; u < TT; u += 8) {
        float v[8];
#pragma unroll
        for (int j = 0; j < 8; ++j) {
            int tt = t0 + u + j;
            v[j] = (valid && tt < T) ? __ldg(src + (size_t)tt * lstride) * LOG2E
                                     : NEGV;
        }
#pragma unroll
        for (int j = 0; j < 8; ++j) {
            int tt = t0 + u + j;
            if (tt < T) g_emit[((size_t)tt * N + n) * 256 + s] = v[j];
        }
    }
}

// ---------------------------------------------------------------------------
// Phase 2: fwd+bwd halves, FOUR warps per CTA with overlapping coverage
// (halo-recompute), 2 states per lane. Warp w covers slots [48w, 48w+64).
// Zones (16 slots) refreshed once per 8-step chunk; chunk bodies are fully
// BRANCHLESS (tail handled separately).
// ---------------------------------------------------------------------------
__device__ __forceinline__ void issue_q(const float* ecov, size_t tstride,
                                        float (*buf)[CHUNK][64], int lane,
                                        int b, int i0, int imax,
                                        bool desc, int tbase) {
    if (lane < 16) {
#pragma unroll
        for (int j = 0; j < CHUNK; ++j) {
            int ii = i0 + j;
            if (ii > imax) ii = imax;
            int tt = desc ? (tbase - ii) : ii;
            const float* src = ecov + (size_t)tt * tstride + lane * 4;
            uint32_t dst = (uint32_t)__cvta_generic_to_shared(&buf[b][j][lane * 4]);
            asm volatile("cp.async.cg.shared.global [%0], [%1], 16;"
                         :: "r"(dst), "l"(src));
        }
    }
    asm volatile("cp.async.commit_group;" ::: "memory");
}

__global__ void __launch_bounds__(128, 1)
fb_kernel(const int* __restrict__ targets,
          const int* __restrict__ il,
          const int* __restrict__ tl,
          float*     __restrict__ out,
          int N, int L) {
    __shared__ float sm_e[4][2][CHUNK][64];   // per-warp emission FIFO
    __shared__ float xfer[2][3][16];          // 3 zone regions, parity buffered

    const bool fwd = (blockIdx.x < (unsigned)N);
    const int  n    = fwd ? blockIdx.x : (blockIdx.x - N);
    const int  w    = threadIdx.x >> 5;
    const int  lane = threadIdx.x & 31;
    const int  S    = 2 * L + 1;

    const int ilen  = il[n];
    const int s_end = 2 * tl[n];
    const int m     = (ilen - 1) >> 1;

    const int covw = 48 * w;
    const int base = covw + lane * 2;

    const float* ecov    = g_emit + (size_t)n * 256 + covw;
    const float* ebase   = g_emit + (size_t)n * 256 + base;
    const size_t tstride = (size_t)N * 256;
    float (*buf)[CHUNK][64] = sm_e[w];

    float a[2];

    if (fwd) {
        bool skip[2];
#pragma unroll
        for (int i = 0; i < 2; ++i) {
            int s = base + i;
            skip[i] = false;
            if (s < S && (s & 1) && s >= 3)
                skip[i] = (__ldg(&targets[n * L + (s >> 1)]) !=
                           __ldg(&targets[n * L + (s >> 1) - 1]));
        }
        {   // t = 0
            float2 E = __ldg((const float2*)ebase);
            a[0] = (base     <= 1) ? E.x : NEGV;
            a[1] = (base + 1 <= 1) ? E.y : NEGV;
        }

        if (m >= 1) {
            issue_q(ecov, tstride, buf, lane, 0, 1, m, false, 0);
            issue_q(ecov, tstride, buf, lane, 1, 1 + CHUNK, m, false, 0);
            int t = 1, b = 0, xb = 0;
            const int nfull = m / CHUNK;
            for (int c = 0; c < nfull; ++c) {
                xb ^= 1;
                if (w < 3 && lane >= 24) {
                    xfer[xb][w][(lane - 24) * 2]     = a[0];
                    xfer[xb][w][(lane - 24) * 2 + 1] = a[1];
                }
                __syncthreads();
                if (w > 0 && lane < 8) {
                    a[0] = xfer[xb][w - 1][lane * 2];
                    a[1] = xfer[xb][w - 1][lane * 2 + 1];
                }
                asm volatile("cp.async.wait_group 1;" ::: "memory");
                __syncwarp();
                float2 E[CHUNK];
#pragma unroll
                for (int j = 0; j < CHUNK; ++j)
                    E[j] = *(const float2*)&buf[b][j][lane * 2];
                __syncwarp();
                issue_q(ecov, tstride, buf, lane, b, t + 2 * CHUNK, m, false, 0);
                b ^= 1;
#pragma unroll
                for (int j = 0; j < CHUNK; ++j) {   // BRANCHLESS body
                    float s1 = __shfl_up_sync(0xffffffffu, a[1], 1);
                    float s0 = __shfl_up_sync(0xffffffffu, a[0], 1);
                    if (lane == 0) { s1 = NEGV; s0 = NEGV; }
                    a[1] = lae3(a[1], a[0], skip[1] ? s1 : NEGV) + E[j].y;
                    a[0] = lae3(a[0], s1,   skip[0] ? s0 : NEGV) + E[j].x;
                }
                t += CHUNK;
            }
            if (t <= m) {   // tail chunk (<= 7 steps)
                xb ^= 1;
                if (w < 3 && lane >= 24) {
                    xfer[xb][w][(lane - 24) * 2]     = a[0];
                    xfer[xb][w][(lane - 24) * 2 + 1] = a[1];
                }
                __syncthreads();
                if (w > 0 && lane < 8) {
                    a[0] = xfer[xb][w - 1][lane * 2];
                    a[1] = xfer[xb][w - 1][lane * 2 + 1];
                }
                asm volatile("cp.async.wait_group 1;" ::: "memory");
                __syncwarp();
                float2 E[CHUNK];
#pragma unroll
                for (int j = 0; j < CHUNK; ++j)
                    E[j] = *(const float2*)&buf[b][j][lane * 2];
#pragma unroll
                for (int j = 0; j < CHUNK; ++j) {
                    if (t <= m) {
                        float s1 = __shfl_up_sync(0xffffffffu, a[1], 1);
                        float s0 = __shfl_up_sync(0xffffffffu, a[0], 1);
                        if (lane == 0) { s1 = NEGV; s0 = NEGV; }
                        a[1] = lae3(a[1], a[0], skip[1] ? s1 : NEGV) + E[j].y;
                        a[0] = lae3(a[0], s1,   skip[0] ? s0 : NEGV) + E[j].x;
                        ++t;
                    }
                }
            }
        }
        // authoritative: w0 all, w>0 lanes >= 8
        if (w == 0 || lane >= 8) {
            g_alpha[n * 256 + base]     = a[0];
            g_alpha[n * 256 + base + 1] = a[1];
        }
        if (w >= 1 && lane < 8) {          // pad 208..255
            int p = 208 + (w - 1) * 16 + lane * 2;
            g_alpha[n * 256 + p]     = NEGV;
            g_alpha[n * 256 + p + 1] = NEGV;
        }
    } else {
        bool bskip[2];
#pragma unroll
        for (int i = 0; i < 2; ++i) {
            int s = base + i;
            bskip[i] = false;
            if (s < S && (s & 1) && (s >> 1) + 1 <= L - 1)
                bskip[i] = (__ldg(&targets[n * L + (s >> 1)]) !=
                            __ldg(&targets[n * L + (s >> 1) + 1]));
        }
        if (ilen == 1) {
#pragma unroll
            for (int i = 0; i < 2; ++i) {
                int s = base + i;
                a[i] = (s == s_end || (s_end >= 1 && s == s_end - 1)) ? 0.0f : NEGV;
            }
        } else {
            {   // init beta at t = ilen-1
                float2 E = __ldg((const float2*)(ebase + (size_t)(ilen - 1) * tstride));
                float e0[2] = {E.x, E.y};
#pragma unroll
                for (int i = 0; i < 2; ++i) {
                    int s = base + i;
                    a[i] = (s == s_end || (s_end >= 1 && s == s_end - 1))
                           ? e0[i] : NEGV;
                }
            }
            const int K = ilen - 2 - m;
            int xb = 0;
            if (K >= 1) {
                issue_q(ecov, tstride, buf, lane, 0, 1, K, true, ilen - 1);
                issue_q(ecov, tstride, buf, lane, 1, 1 + CHUNK, K, true, ilen - 1);
                int k = 1, b = 0;
                const int nfull = K / CHUNK;
                for (int c = 0; c < nfull; ++c) {
                    xb ^= 1;
                    if (w >= 1 && lane < 8) {
                        xfer[xb][w - 1][lane * 2]     = a[0];
                        xfer[xb][w - 1][lane * 2 + 1] = a[1];
                    }
                    __syncthreads();
                    if (w < 3 && lane >= 24) {
                        a[0] = xfer[xb][w][(lane - 24) * 2];
                        a[1] = xfer[xb][w][(lane - 24) * 2 + 1];
                    }
                    asm volatile("cp.async.wait_group 1;" ::: "memory");
                    __syncwarp();
                    float2 E[CHUNK];
#pragma unroll
                    for (int j = 0; j < CHUNK; ++j)
                        E[j] = *(const float2*)&buf[b][j][lane * 2];
                    __syncwarp();
                    issue_q(ecov, tstride, buf, lane, b, k + 2 * CHUNK, K,
                            true, ilen - 1);
                    b ^= 1;
#pragma unroll
                    for (int j = 0; j < CHUNK; ++j) {   // BRANCHLESS body
                        float d0 = __shfl_down_sync(0xffffffffu, a[0], 1);
                        float d1 = __shfl_down_sync(0xffffffffu, a[1], 1);
                        if (lane == 31) { d0 = NEGV; d1 = NEGV; }
                        a[0] = lae3(a[0], a[1], bskip[0] ? d0 : NEGV) + E[j].x;
                        a[1] = lae3(a[1], d0,   bskip[1] ? d1 : NEGV) + E[j].y;
                    }
                    k += CHUNK;
                }
                if (k <= K) {   // tail chunk
                    xb ^= 1;
                    if (w >= 1 && lane < 8) {
                        xfer[xb][w - 1][lane * 2]     = a[0];
                        xfer[xb][w - 1][lane * 2 + 1] = a[1];
                    }
                    __syncthreads();
                    if (w < 3 && lane >= 24) {
                        a[0] = xfer[xb][w][(lane - 24) * 2];
                        a[1] = xfer[xb][w][(lane - 24) * 2 + 1];
                    }
                    asm volatile("cp.async.wait_group 1;" ::: "memory");
                    __syncwarp();
                    float2 E[CHUNK];
#pragma unroll
                    for (int j = 0; j < CHUNK; ++j)
                        E[j] = *(const float2*)&buf[b][j][lane * 2];
#pragma unroll
                    for (int j = 0; j < CHUNK; ++j) {
                        if (k <= K) {
                            float d0 = __shfl_down_sync(0xffffffffu, a[0], 1);
                            float d1 = __shfl_down_sync(0xffffffffu, a[1], 1);
                            if (lane == 31) { d0 = NEGV; d1 = NEGV; }
                            a[0] = lae3(a[0], a[1], bskip[0] ? d0 : NEGV) + E[j].x;
                            a[1] = lae3(a[1], d0,   bskip[1] ? d1 : NEGV) + E[j].y;
                            ++k;
                        }
                    }
                }
            }
            // final zone exchange before gamma
            xb ^= 1;
            if (w >= 1 && lane < 8) {
                xfer[xb][w - 1][lane * 2]     = a[0];
                xfer[xb][w - 1][lane * 2 + 1] = a[1];
            }
            __syncthreads();
            if (w < 3 && lane >= 24) {
                a[0] = xfer[xb][w][(lane - 24) * 2];
                a[1] = xfer[xb][w][(lane - 24) * 2 + 1];
            }
            {   // gamma: one transition-only step
                float d0 = __shfl_down_sync(0xffffffffu, a[0], 1);
                float d1 = __shfl_down_sync(0xffffffffu, a[1], 1);
                if (lane == 31) { d0 = NEGV; d1 = NEGV; }
                a[0] = lae3(a[0], a[1], bskip[0] ? d0 : NEGV);
                a[1] = lae3(a[1], d0,   bskip[1] ? d1 : NEGV);
            }
        }
        // authoritative: w3 all, w<3 lanes < 24
        if (w == 3 || lane < 24) {
            g_gamma[n * 256 + base]     = a[0];
            g_gamma[n * 256 + base + 1] = a[1];
        }
        if (w < 3 && lane >= 24) {         // pad 208..255
            int p = 208 + w * 16 + (lane - 24) * 2;
            g_gamma[n * 256 + p]     = NEGV;
            g_gamma[n * 256 + p + 1] = NEGV;
        }
    }

    // ---- finisher: last block combines (per-n logsumexp) + fixed-order sum ----
    __threadfence();
    unsigned done = 0;
    if (threadIdx.x == 0)
        done = (atomicAdd(&g_fb_ctr, 1u) == (unsigned)(2 * N) - 1u);
    done = __shfl_sync(0xffffffffu, done, 0);
    if (w == 0 && done) {
        __threadfence();
        float acc = 0.0f;
        for (int nn = 0; nn < N; ++nn) {
            float v[8];
            float mx = -3.4e38f;
#pragma unroll
            for (int k = 0; k < 8; ++k) {
                v[k] = g_alpha[nn * 256 + lane + 32 * k]
                     + g_gamma[nn * 256 + lane + 32 * k];
                mx = fmaxf(mx, v[k]);
            }
#pragma unroll
            for (int o = 16; o > 0; o >>= 1)
                mx = fmaxf(mx, __shfl_xor_sync(0xffffffffu, mx, o));
            float sum = 0.0f;
#pragma unroll
            for (int k = 0; k < 8; ++k)
                sum += (v[k] - mx > -120.0f) ? ex2f(v[k] - mx) : 0.0f;
#pragma unroll
            for (int o = 16; o > 0; o >>= 1)
                sum += __shfl_xor_sync(0xffffffffu, sum, o);
            float tot = (mx + lg2f(sum)) * LN2;
            if (lane == 0 && tot > -1e29f) acc += tot;
        }
        if (lane == 0) {
            out[0] = -acc;
            g_fb_ctr = 0u;
            __threadfence();
        }
    }
}

extern "C" void kernel_launch(void* const* d_in, const int* in_sizes, int n_in,
                              void* d_out, int out_size) {
    const float* lp      = (const float*)d_in[0];
    const int*   targets = (const int*)d_in[1];
    const int*   il      = (const int*)d_in[2];
    const int*   tl      = (const int*)d_in[3];

    const int N = in_sizes[2];
    const int L = in_sizes[1] / N;        // 100
    const int C = 1024;                   // fixed for this problem id
    const int T = in_sizes[0] / (N * C);  // 1500
    const int S = 2 * L + 1;              // 201 (needs S <= 208)

    dim3 ggrid((T + TT - 1) / TT, N);
    gather_kernel<<<ggrid, 256>>>(lp, targets, N, C, L, S, T);
    fb_kernel<<<2 * N, 128>>>(targets, il, tl, (float*)d_out, N, L);
}

// round 16
// speedup vs baseline: 3.4973x; 1.0184x over previous
#include <cuda_runtime.h>
#include <cstdint>

#define NEGV (-1e30f)
#define LOG2E 1.4426950408889634f
#define LN2   0.6931471805599453f
#define CHUNK 8
#define TT    64            // t-tile per gather block

// Static device scratch (allocation APIs are forbidden).
__device__ float    g_emit[12u * 1024u * 1024u];  // e[t][n][256], slot = state
__device__ float    g_alpha[1024 * 256];
__device__ float    g_gamma[1024 * 256];
__device__ unsigned g_fb_ctr;                      // zero-init; reset each call

__device__ __forceinline__ float ex2f(float x) {
    float y; asm("ex2.approx.ftz.f32 %0, %1;" : "=f"(y) : "f"(x)); return y;
}
__device__ __forceinline__ float lg2f(float x) {
    float y; asm("lg2.approx.ftz.f32 %0, %1;" : "=f"(y) : "f"(x)); return y;
}
// x2 is the late-arriving operand (shfl) -> keep it shallow in the trees.
__device__ __forceinline__ float lae3(float x0, float x1, float x2) {
    float m01 = fmaxf(x0, x1), n01 = fminf(x0, x1);
    float hi  = fmaxf(m01, x2);
    float lo  = fminf(n01, x2);
    float md  = fmaxf(n01, fminf(m01, x2));
    return hi + lg2f(1.0f + ex2f(md - hi) + ex2f(lo - hi));
}
// 2-way logaddexp (log2 domain) for blank (even) states: no skip edge.
__device__ __forceinline__ float lae2(float x0, float x1) {
    float hi = fmaxf(x0, x1);
    float lo = fminf(x0, x1);
    return hi + lg2f(1.0f + ex2f(lo - hi));
}

// ---------------------------------------------------------------------------
// Phase 1: emission gather. block = (t-tile, n); label resolved once per
// thread, then 64 t's streamed with an 8-deep MLP ring.
// ---------------------------------------------------------------------------
__global__ void gather_kernel(const float* __restrict__ lp,
                              const int*   __restrict__ targets,
                              int N, int C, int L, int S, int T) {
    const int n  = blockIdx.y;
    const int t0 = blockIdx.x * TT;
    const int s  = threadIdx.x;           // slot == state, 0..255

    const bool valid = (s < S);
    int lab = 0;
    if (valid && (s & 1)) lab = __ldg(&targets[n * L + (s >> 1)]);
    const float* src = lp + (size_t)n * C + lab;
    const size_t lstride = (size_t)N * C;

    for (int u = 0; u < TT; u += 8) {
        float v[8];
#pragma unroll
        for (int j = 0; j < 8; ++j) {
            int tt = t0 + u + j;
            v[j] = (valid && tt < T) ? __ldg(src + (size_t)tt * lstride) * LOG2E
                                     : NEGV;
        }
#pragma unroll
        for (int j = 0; j < 8; ++j) {
            int tt = t0 + u + j;
            if (tt < T) g_emit[((size_t)tt * N + n) * 256 + s] = v[j];
        }
    }
}

// ---------------------------------------------------------------------------
// Phase 2: fwd+bwd halves, FOUR warps per CTA with overlapping coverage
// (halo-recompute), 2 states per lane (even = blank -> lae2, no skip).
// Warp w covers slots [48w, 48w+64); 16-slot zones refreshed per 8-step
// chunk; chunk bodies branchless.
// ---------------------------------------------------------------------------
__device__ __forceinline__ void issue_q(const float* ecov, size_t tstride,
                                        float (*buf)[CHUNK][64], int lane,
                                        int b, int i0, int imax,
                                        bool desc, int tbase) {
    if (lane < 16) {
#pragma unroll
        for (int j = 0; j < CHUNK; ++j) {
            int ii = i0 + j;
            if (ii > imax) ii = imax;
            int tt = desc ? (tbase - ii) : ii;
            const float* src = ecov + (size_t)tt * tstride + lane * 4;
            uint32_t dst = (uint32_t)__cvta_generic_to_shared(&buf[b][j][lane * 4]);
            asm volatile("cp.async.cg.shared.global [%0], [%1], 16;"
                         :: "r"(dst), "l"(src));
        }
    }
    asm volatile("cp.async.commit_group;" ::: "memory");
}

__global__ void __launch_bounds__(128, 1)
fb_kernel(const int* __restrict__ targets,
          const int* __restrict__ il,
          const int* __restrict__ tl,
          float*     __restrict__ out,
          int N, int L) {
    __shared__ float sm_e[4][2][CHUNK][64];   // per-warp emission FIFO
    __shared__ float xfer[2][3][16];          // 3 zone regions, parity buffered

    const bool fwd = (blockIdx.x < (unsigned)N);
    const int  n    = fwd ? blockIdx.x : (blockIdx.x - N);
    const int  w    = threadIdx.x >> 5;
    const int  lane = threadIdx.x & 31;
    const int  S    = 2 * L + 1;

    const int ilen  = il[n];
    const int s_end = 2 * tl[n];
    const int m     = (ilen - 1) >> 1;

    const int covw = 48 * w;
    const int base = covw + lane * 2;     // even -> a[0] is a blank state

    const float* ecov    = g_emit + (size_t)n * 256 + covw;
    const float* ebase   = g_emit + (size_t)n * 256 + base;
    const size_t tstride = (size_t)N * 256;
    float (*buf)[CHUNK][64] = sm_e[w];

    float a[2];

    if (fwd) {
        bool skip1 = false;               // skip edge for the odd state base+1
        {
            int s = base + 1;
            if (s < S && s >= 3)
                skip1 = (__ldg(&targets[n * L + (s >> 1)]) !=
                         __ldg(&targets[n * L + (s >> 1) - 1]));
        }
        {   // t = 0
            float2 E = __ldg((const float2*)ebase);
            a[0] = (base     <= 1) ? E.x : NEGV;
            a[1] = (base + 1 <= 1) ? E.y : NEGV;
        }

        if (m >= 1) {
            issue_q(ecov, tstride, buf, lane, 0, 1, m, false, 0);
            issue_q(ecov, tstride, buf, lane, 1, 1 + CHUNK, m, false, 0);
            int t = 1, b = 0, xb = 0;
            const int nfull = m / CHUNK;
            for (int c = 0; c < nfull; ++c) {
                xb ^= 1;
                if (w < 3 && lane >= 24) {
                    xfer[xb][w][(lane - 24) * 2]     = a[0];
                    xfer[xb][w][(lane - 24) * 2 + 1] = a[1];
                }
                __syncthreads();
                if (w > 0 && lane < 8) {
                    a[0] = xfer[xb][w - 1][lane * 2];
                    a[1] = xfer[xb][w - 1][lane * 2 + 1];
                }
                asm volatile("cp.async.wait_group 1;" ::: "memory");
                __syncwarp();
                float2 E[CHUNK];
#pragma unroll
                for (int j = 0; j < CHUNK; ++j)
                    E[j] = *(const float2*)&buf[b][j][lane * 2];
                __syncwarp();
                issue_q(ecov, tstride, buf, lane, b, t + 2 * CHUNK, m, false, 0);
                b ^= 1;
#pragma unroll
                for (int j = 0; j < CHUNK; ++j) {   // branchless, 1 shfl
                    float s1 = __shfl_up_sync(0xffffffffu, a[1], 1);
                    if (lane == 0) s1 = NEGV;
                    float a1n = lae3(a[1], a[0], skip1 ? s1 : NEGV) + E[j].y;
                    a[0] = lae2(a[0], s1) + E[j].x;
                    a[1] = a1n;
                }
                t += CHUNK;
            }
            if (t <= m) {   // tail chunk (<= 7 steps)
                xb ^= 1;
                if (w < 3 && lane >= 24) {
                    xfer[xb][w][(lane - 24) * 2]     = a[0];
                    xfer[xb][w][(lane - 24) * 2 + 1] = a[1];
                }
                __syncthreads();
                if (w > 0 && lane < 8) {
                    a[0] = xfer[xb][w - 1][lane * 2];
                    a[1] = xfer[xb][w - 1][lane * 2 + 1];
                }
                asm volatile("cp.async.wait_group 1;" ::: "memory");
                __syncwarp();
                float2 E[CHUNK];
#pragma unroll
                for (int j = 0; j < CHUNK; ++j)
                    E[j] = *(const float2*)&buf[b][j][lane * 2];
#pragma unroll
                for (int j = 0; j < CHUNK; ++j) {
                    if (t <= m) {
                        float s1 = __shfl_up_sync(0xffffffffu, a[1], 1);
                        if (lane == 0) s1 = NEGV;
                        float a1n = lae3(a[1], a[0], skip1 ? s1 : NEGV) + E[j].y;
                        a[0] = lae2(a[0], s1) + E[j].x;
                        a[1] = a1n;
                        ++t;
                    }
                }
            }
        }
        // authoritative: w0 all, w>0 lanes >= 8
        if (w == 0 || lane >= 8) {
            g_alpha[n * 256 + base]     = a[0];
            g_alpha[n * 256 + base + 1] = a[1];
        }
        if (w >= 1 && lane < 8) {          // pad 208..255
            int p = 208 + (w - 1) * 16 + lane * 2;
            g_alpha[n * 256 + p]     = NEGV;
            g_alpha[n * 256 + p + 1] = NEGV;
        }
    } else {
        bool bskip1 = false;               // skip-out edge for odd state base+1
        {
            int s = base + 1;
            if (s < S && (s >> 1) + 1 <= L - 1)
                bskip1 = (__ldg(&targets[n * L + (s >> 1)]) !=
                          __ldg(&targets[n * L + (s >> 1) + 1]));
        }
        if (ilen == 1) {
#pragma unroll
            for (int i = 0; i < 2; ++i) {
                int s = base + i;
                a[i] = (s == s_end || (s_end >= 1 && s == s_end - 1)) ? 0.0f : NEGV;
            }
        } else {
            {   // init beta at t = ilen-1
                float2 E = __ldg((const float2*)(ebase + (size_t)(ilen - 1) * tstride));
                float e0[2] = {E.x, E.y};
#pragma unroll
                for (int i = 0; i < 2; ++i) {
                    int s = base + i;
                    a[i] = (s == s_end || (s_end >= 1 && s == s_end - 1))
                           ? e0[i] : NEGV;
                }
            }
            const int K = ilen - 2 - m;
            int xb = 0;
            if (K >= 1) {
                issue_q(ecov, tstride, buf, lane, 0, 1, K, true, ilen - 1);
                issue_q(ecov, tstride, buf, lane, 1, 1 + CHUNK, K, true, ilen - 1);
                int k = 1, b = 0;
                const int nfull = K / CHUNK;
                for (int c = 0; c < nfull; ++c) {
                    xb ^= 1;
                    if (w >= 1 && lane < 8) {
                        xfer[xb][w - 1][lane * 2]     = a[0];
                        xfer[xb][w - 1][lane * 2 + 1] = a[1];
                    }
                    __syncthreads();
                    if (w < 3 && lane >= 24) {
                        a[0] = xfer[xb][w][(lane - 24) * 2];
                        a[1] = xfer[xb][w][(lane - 24) * 2 + 1];
                    }
                    asm volatile("cp.async.wait_group 1;" ::: "memory");
                    __syncwarp();
                    float2 E[CHUNK];
#pragma unroll
                    for (int j = 0; j < CHUNK; ++j)
                        E[j] = *(const float2*)&buf[b][j][lane * 2];
                    __syncwarp();
                    issue_q(ecov, tstride, buf, lane, b, k + 2 * CHUNK, K,
                            true, ilen - 1);
                    b ^= 1;
#pragma unroll
                    for (int j = 0; j < CHUNK; ++j) {   // branchless
                        float d0 = __shfl_down_sync(0xffffffffu, a[0], 1);
                        float d1 = __shfl_down_sync(0xffffffffu, a[1], 1);
                        if (lane == 31) { d0 = NEGV; d1 = NEGV; }
                        float a0n = lae2(a[0], a[1]) + E[j].x;   // no shfl dep
                        a[1] = lae3(a[1], d0, bskip1 ? d1 : NEGV) + E[j].y;
                        a[0] = a0n;
                    }
                    k += CHUNK;
                }
                if (k <= K) {   // tail chunk
                    xb ^= 1;
                    if (w >= 1 && lane < 8) {
                        xfer[xb][w - 1][lane * 2]     = a[0];
                        xfer[xb][w - 1][lane * 2 + 1] = a[1];
                    }
                    __syncthreads();
                    if (w < 3 && lane >= 24) {
                        a[0] = xfer[xb][w][(lane - 24) * 2];
                        a[1] = xfer[xb][w][(lane - 24) * 2 + 1];
                    }
                    asm volatile("cp.async.wait_group 1;" ::: "memory");
                    __syncwarp();
                    float2 E[CHUNK];
#pragma unroll
                    for (int j = 0; j < CHUNK; ++j)
                        E[j] = *(const float2*)&buf[b][j][lane * 2];
#pragma unroll
                    for (int j = 0; j < CHUNK; ++j) {
                        if (k <= K) {
                            float d0 = __shfl_down_sync(0xffffffffu, a[0], 1);
                            float d1 = __shfl_down_sync(0xffffffffu, a[1], 1);
                            if (lane == 31) { d0 = NEGV; d1 = NEGV; }
                            float a0n = lae2(a[0], a[1]) + E[j].x;
                            a[1] = lae3(a[1], d0, bskip1 ? d1 : NEGV) + E[j].y;
                            a[0] = a0n;
                            ++k;
                        }
                    }
                }
            }
            // final zone exchange before gamma
            xb ^= 1;
            if (w >= 1 && lane < 8) {
                xfer[xb][w - 1][lane * 2]     = a[0];
                xfer[xb][w - 1][lane * 2 + 1] = a[1];
            }
            __syncthreads();
            if (w < 3 && lane >= 24) {
                a[0] = xfer[xb][w][(lane - 24) * 2];
                a[1] = xfer[xb][w][(lane - 24) * 2 + 1];
            }
            {   // gamma: one transition-only step
                float d0 = __shfl_down_sync(0xffffffffu, a[0], 1);
                float d1 = __shfl_down_sync(0xffffffffu, a[1], 1);
                if (lane == 31) { d0 = NEGV; d1 = NEGV; }
                float a0n = lae2(a[0], a[1]);
                a[1] = lae3(a[1], d0, bskip1 ? d1 : NEGV);
                a[0] = a0n;
            }
        }
        // authoritative: w3 all, w<3 lanes < 24
        if (w == 3 || lane < 24) {
            g_gamma[n * 256 + base]     = a[0];
            g_gamma[n * 256 + base + 1] = a[1];
        }
        if (w < 3 && lane >= 24) {         // pad 208..255
            int p = 208 + w * 16 + (lane - 24) * 2;
            g_gamma[n * 256 + p]     = NEGV;
            g_gamma[n * 256 + p + 1] = NEGV;
        }
    }

    // ---- finisher: last block combines (per-n logsumexp) + fixed-order sum ----
    __threadfence();
    unsigned done = 0;
    if (threadIdx.x == 0)
        done = (atomicAdd(&g_fb_ctr, 1u) == (unsigned)(2 * N) - 1u);
    done = __shfl_sync(0xffffffffu, done, 0);
    if (w == 0 && done) {
        __threadfence();
        float acc = 0.0f;
        for (int nn = 0; nn < N; ++nn) {
            float v[8];
            float mx = -3.4e38f;
#pragma unroll
            for (int k = 0; k < 8; ++k) {
                v[k] = g_alpha[nn * 256 + lane + 32 * k]
                     + g_gamma[nn * 256 + lane + 32 * k];
                mx = fmaxf(mx, v[k]);
            }
#pragma unroll
            for (int o = 16; o > 0; o >>= 1)
                mx = fmaxf(mx, __shfl_xor_sync(0xffffffffu, mx, o));
            float sum = 0.0f;
#pragma unroll
            for (int k = 0; k < 8; ++k)
                sum += (v[k] - mx > -120.0f) ? ex2f(v[k] - mx) : 0.0f;
#pragma unroll
            for (int o = 16; o > 0; o >>= 1)
                sum += __shfl_xor_sync(0xffffffffu, sum, o);
            float tot = (mx + lg2f(sum)) * LN2;
            if (lane == 0 && tot > -1e29f) acc += tot;
        }
        if (lane == 0) {
            out[0] = -acc;
            g_fb_ctr = 0u;
            __threadfence();
        }
    }
}

extern "C" void kernel_launch(void* const* d_in, const int* in_sizes, int n_in,
                              void* d_out, int out_size) {
    const float* lp      = (const float*)d_in[0];
    const int*   targets = (const int*)d_in[1];
    const int*   il      = (const int*)d_in[2];
    const int*   tl      = (const int*)d_in[3];

    const int N = in_sizes[2];
    const int L = in_sizes[1] / N;        // 100
    const int C = 1024;                   // fixed for this problem id
    const int T = in_sizes[0] / (N * C);  // 1500
    const int S = 2 * L + 1;              // 201 (needs S <= 208)

    dim3 ggrid((T + TT - 1) / TT, N);
    gather_kernel<<<ggrid, 256>>>(lp, targets, N, C, L, S, T);
    fb_kernel<<<2 * N, 128>>>(targets, il, tl, (float*)d_out, N, L);
}